// round 11
// baseline (speedup 1.0000x reference)
#include <cuda_runtime.h>
#include <math.h>

#define B   64
#define S   96
#define E   300
#define H   256
#define D   512
#define SEL 128
#define G5  1280
#define MLPD 1024
#define NC  3

#define CL  8      // cluster size
#define NB  4      // batches per cluster
#define NCL 16     // clusters
#define TPB 640
#define NS  97     // S + 1 spare slot per batch

typedef unsigned long long ull;

__device__ __align__(16) float g_states[B][NS][D];
__device__ float g_logits0[B][S - 1];
__device__ float g_hroot[B][H];
__device__ float g_x1[B][MLPD];
__device__ float g_x2[B][MLPD];

__device__ __forceinline__ float sigf(float x) { return 1.0f / (1.0f + expf(-x)); }
__device__ __forceinline__ ull fma2(ull a, ull b, ull c) {
    ull d; asm("fma.rn.f32x2 %0, %1, %2, %3;" : "=l"(d) : "l"(a), "l"(b), "l"(c)); return d;
}
__device__ __forceinline__ ull add2(ull a, ull b) {
    ull d; asm("add.rn.f32x2 %0, %1, %2;" : "=l"(d) : "l"(a), "l"(b)); return d;
}
__device__ __forceinline__ ull pack2(float x, float y) {
    ull d; asm("mov.b64 %0, {%1, %2};" : "=l"(d) : "f"(x), "f"(y)); return d;
}
__device__ __forceinline__ float lo32(ull v) { return __uint_as_float((unsigned)v); }
__device__ __forceinline__ float hi32(ull v) { return __uint_as_float((unsigned)(v >> 32)); }

__device__ __forceinline__ unsigned smem_u32(const void* p) {
    return (unsigned)__cvta_generic_to_shared(p);
}
__device__ __forceinline__ void stc_f32(unsigned laddr, int rank, float v) {
    unsigned ra;
    asm volatile("mapa.shared::cluster.u32 %0, %1, %2;" : "=r"(ra) : "r"(laddr), "r"(rank));
    asm volatile("st.shared::cluster.f32 [%0], %1;" :: "r"(ra), "f"(v));
}
__device__ __forceinline__ void cluster_bar() {
    asm volatile("barrier.cluster.arrive.release.aligned;" ::: "memory");
    asm volatile("barrier.cluster.wait.acquire.aligned;" ::: "memory");
}

// ---- dynamic smem layout (bytes) ----
#define O_XS2   0        // ull  xs2[4][512]         16384
#define O_XP    16384    // ull  xp[4][512]          16384
#define O_REDK  32768    // ull  redk[160][8]        10240
#define O_P5Q   43008    // ull  p5q[512]            4096
#define O_WS1S  47104    // float Ws1s[16][524]      33536
#define O_BCS   80640    // float bcs[160]           640
#define O_LG    81280    // float lg[4][96]          1536
#define O_PM    82816    // int  pm[4][96]           1536
#define O_MISC  84352    // ints/floats              512
#define O_CLCR  84864    // float clcr[4][2][32]     1024
#define O_XNL   85888    // float xnl[4][256]        4096
#define O_XNR   89984    // float xnr[4][256]        4096
#define O_HM    94080    // float hM[4][256]         4096
#define O_P5A   98176    // float p5a[8][8]          256
#define SMEM_SZ 98432

__global__ void prof_pad_kernel() {}

// ======================================================================
__global__ void encode_kernel(const int* __restrict__ sent, const float* __restrict__ emb,
                              const float* __restrict__ Wenc, const float* __restrict__ benc) {
    __shared__ float xsh[8][E];
    __shared__ int tok[8];
    int row0 = blockIdx.x * 8, tid = threadIdx.x;
    if (tid < 8) tok[tid] = sent[row0 + tid];
    __syncthreads();
    for (int i = tid; i < 8 * E; i += 128) {
        int r = i / E, k = i - r * E;
        xsh[r][k] = emb[(long)tok[r] * E + k];
    }
    __syncthreads();
    int c = tid * 4;
    float4 acc[8];
#pragma unroll
    for (int r = 0; r < 8; r++) acc[r] = make_float4(0.f, 0.f, 0.f, 0.f);
    for (int k = 0; k < E; k++) {
        float4 w = *(const float4*)&Wenc[k * D + c];
#pragma unroll
        for (int r = 0; r < 8; r++) {
            float xv = xsh[r][k];
            acc[r].x = __fmaf_rn(xv, w.x, acc[r].x); acc[r].y = __fmaf_rn(xv, w.y, acc[r].y);
            acc[r].z = __fmaf_rn(xv, w.z, acc[r].z); acc[r].w = __fmaf_rn(xv, w.w, acc[r].w);
        }
    }
    float4 bv = *(const float4*)&benc[c];
#pragma unroll
    for (int r = 0; r < 8; r++) {
        acc[r].x += bv.x; acc[r].y += bv.y; acc[r].z += bv.z; acc[r].w += bv.w;
        int gr = row0 + r, b = gr / S, s = gr - b * S;
        *(float4*)&g_states[b][s][c] = acc[r];
    }
}

// ======================================================================
__global__ void initsel_kernel(const float* __restrict__ Ws1, const float* __restrict__ bs1,
                               const float* __restrict__ Ws2, const float* __restrict__ bs2) {
    __shared__ float hs[17][H];
    __shared__ float red[4];
    int b = blockIdx.y, p0 = blockIdx.x * 16, tid = threadIdx.x;
    int nrows = min(17, S - p0);
    for (int i = tid; i < nrows * H; i += 128) {
        int r = i >> 8, k = i & (H - 1);
        hs[r][k] = g_states[b][p0 + r][H + k];
    }
    __syncthreads();
    int npairs = min(16, (S - 1) - p0);
    for (int p = 0; p < npairs; p++) {
        float a[8];
#pragma unroll
        for (int m = 0; m < 8; m++) a[m] = 0.0f;
        const float* wp = Ws1 + tid;
        for (int k = 0; k < 64; k++) {
#pragma unroll
            for (int m = 0; m < 4; m++)
                a[m] = __fmaf_rn(hs[p][m * 64 + k], wp[(m * 64 + k) * SEL], a[m]);
#pragma unroll
            for (int m = 0; m < 4; m++)
                a[4 + m] = __fmaf_rn(hs[p + 1][m * 64 + k], wp[(256 + m * 64 + k) * SEL], a[4 + m]);
        }
        float s = a[0] + a[1] + a[2] + a[3] + a[4] + a[5] + a[6] + a[7] + bs1[tid];
        float y = tanhf(s) * Ws2[tid];
        for (int o = 16; o; o >>= 1) y += __shfl_xor_sync(0xffffffffu, y, o);
        if ((tid & 31) == 0) red[tid >> 5] = y;
        __syncthreads();
        if (tid == 0) g_logits0[b][p0 + p] = red[0] + red[1] + red[2] + red[3] + bs2[0];
        __syncthreads();
    }
}

// ======================================================================
// Scan: 128 CTAs = 16 clusters x 8, 4 batches/cluster.
// CTA r: gate cols h in [32r,32r+32); sel j in [16r,16r+16).
// ======================================================================
__global__ void __cluster_dims__(CL, 1, 1) __launch_bounds__(TPB, 1)
scan_kernel(const float* __restrict__ Wc,  const float* __restrict__ bc,
            const float* __restrict__ Ws1, const float* __restrict__ bs1,
            const float* __restrict__ Ws2, const float* __restrict__ bs2) {
    extern __shared__ char dsm[];
    ull*   xs2  = (ull*)(dsm + O_XS2);
    ull*   xp   = (ull*)(dsm + O_XP);
    ull*   redk = (ull*)(dsm + O_REDK);
    ull*   p5q  = (ull*)(dsm + O_P5Q);
    float* Ws1s = (float*)(dsm + O_WS1S);
    float* bcs  = (float*)(dsm + O_BCS);
    float* lg   = (float*)(dsm + O_LG);
    int*   pmi  = (int*)(dsm + O_PM);
    int*   misc = (int*)(dsm + O_MISC);
    float* clcr = (float*)(dsm + O_CLCR);
    float* xnl  = (float*)(dsm + O_XNL);
    float* xnr  = (float*)(dsm + O_XNR);
    float* hM   = (float*)(dsm + O_HM);
    float* p5a  = (float*)(dsm + O_P5A);   // [rank][8] = rank*8 + b*2 + s
    int* selidx = misc;        int* sLa = misc + 8;   int* sRa = misc + 16;
    int* frs    = misc + 24;   int* fsl = misc + 32;
    float* bs1s = (float*)(misc + 40);
    float* ws2s = (float*)(misc + 56);

    int tid = threadIdx.x;
    int r   = blockIdx.x & (CL - 1);
    int gb0 = (blockIdx.x >> 3) * NB;

    // ---- one-time preloads ----
    for (int i = tid; i < 512 * 16; i += TPB) {
        int k = i >> 4, j16 = i & 15;
        Ws1s[j16 * 524 + k] = Ws1[(size_t)k * SEL + r * 16 + j16];
    }
    if (tid < 160) bcs[tid] = bc[(tid >> 5) * 256 + r * 32 + (tid & 31)];
    if (tid < 16) { bs1s[tid] = bs1[r * 16 + tid]; ws2s[tid] = Ws2[r * 16 + tid]; }
    if (tid < NB) frs[tid] = 96;
    for (int i = tid; i < NB * (S - 1); i += TPB) {
        int b = i / (S - 1), j = i - b * (S - 1);
        lg[b * 96 + j] = g_logits0[gb0 + b][j];
    }
    for (int i = tid; i < NB * S; i += TPB) {
        int b = i / S, j = i - b * S;
        pmi[b * 96 + j] = j;
    }
    float bs2v = bs2[0];
    __syncthreads();

    // compose geometry
    int wid = tid >> 5, lane = tid & 31;
    int cg  = wid % 5, ckb = wid / 5;
    int cks = lane >> 3, cu4 = lane & 7;
    const float* wpc = Wc + cg * 256 + r * 32 + cu4 * 4;
    int ck0 = ckb * 128 + cks * 2;

    for (int t = 0; t < S - 1; t++) {
        int n = S - t, np = n - 1;

        // ---- argmax (replicated): 4 batches x 32 lanes ----
        if (tid < 128) {
            int b = tid >> 5, ln = tid & 31;
            float best = -1e30f; int bi = 0;
            for (int j = ln; j < np; j += 32) {
                float v = lg[b * 96 + j];
                if (v > best) { best = v; bi = j; }
            }
            for (int o = 16; o; o >>= 1) {
                float ov = __shfl_xor_sync(0xffffffffu, best, o);
                int   oi = __shfl_xor_sync(0xffffffffu, bi, o);
                if (ov > best || (ov == best && oi < bi)) { best = ov; bi = oi; }
            }
            if (ln == 0) {
                int sl = pmi[b * 96 + bi], sr = pmi[b * 96 + bi + 1];
                selidx[b] = bi; sLa[b] = sl; sRa[b] = sr;
                fsl[b] = frs[b];
                frs[b] = sr;
            }
        }
        __syncthreads();

        // ---- staging: xs2 (vectorized) + clcr + early neighbor h ----
        for (int i = tid; i < NB * 128; i += TPB) {
            int b = i >> 7, k = (i & 127) << 2;
            int slot = (k < H) ? sLa[b] : sRa[b];
            int col  = (k < H) ? (H + k) : k;
            float4 v = __ldcg((const float4*)&g_states[gb0 + b][slot][col]);
            xs2[b * 512 + k]     = pack2(v.x, v.x);
            xs2[b * 512 + k + 1] = pack2(v.y, v.y);
            xs2[b * 512 + k + 2] = pack2(v.z, v.z);
            xs2[b * 512 + k + 3] = pack2(v.w, v.w);
        }
        if (tid < 256) {
            int b = tid >> 6, half = (tid >> 5) & 1, u = tid & 31;
            clcr[(b * 2 + half) * 32 + u] =
                __ldcg(&g_states[gb0 + b][half ? sRa[b] : sLa[b]][r * 32 + u]);
        }
        for (int i = tid; i < NB * 64; i += TPB) {     // neighbor h, float4
            int b = i >> 6, k = (i & 63) << 2;
            int idx = selidx[b];
            float4 vL = make_float4(0.f, 0.f, 0.f, 0.f), vR = vL;
            if (idx >= 1)
                vL = __ldcg((const float4*)&g_states[gb0 + b][pmi[b * 96 + idx - 1]][H + k]);
            if (idx <= n - 3)
                vR = __ldcg((const float4*)&g_states[gb0 + b][pmi[b * 96 + idx + 2]][H + k]);
            *(float4*)&xnl[b * 256 + k] = vL;
            *(float4*)&xnr[b * 256 + k] = vR;
        }
        __syncthreads();

        // ---- compose: 4 cols x 4 batches x 32 k per thread ----
        {
            ull acc[8];
#pragma unroll
            for (int i = 0; i < 8; i++) acc[i] = 0ull;
#pragma unroll 4
            for (int m = 0; m < 16; m++) {
                int k = ck0 + m * 8;
                ulonglong2 w0 = *(const ulonglong2*)(wpc + (size_t)k * G5);
                ulonglong2 w1 = *(const ulonglong2*)(wpc + (size_t)(k + 1) * G5);
#pragma unroll
                for (int b = 0; b < NB; b++) {
                    ulonglong2 xv = *(const ulonglong2*)&xs2[b * 512 + k];
                    acc[b * 2]     = fma2(w0.x, xv.x, acc[b * 2]);
                    acc[b * 2 + 1] = fma2(w0.y, xv.x, acc[b * 2 + 1]);
                    acc[b * 2]     = fma2(w1.x, xv.y, acc[b * 2]);
                    acc[b * 2 + 1] = fma2(w1.y, xv.y, acc[b * 2 + 1]);
                }
            }
#pragma unroll
            for (int i = 0; i < 8; i++) {
                acc[i] = add2(acc[i], __shfl_xor_sync(0xffffffffu, acc[i], 8));
                acc[i] = add2(acc[i], __shfl_xor_sync(0xffffffffu, acc[i], 16));
            }
            if (cks == 0) {
                ull* dst = &redk[(size_t)(wid * 8 + cu4) * 8];
#pragma unroll
                for (int i = 0; i < 8; i++) dst[i] = acc[i];
            }
        }
        __syncthreads();

        // ---- gates (tid<128, + DSMEM h' bcast) overlapped with shift-read ----
        int spv0 = 0, swp0 = 0, swl0 = 0; float slv0 = 0.f; int sb0 = 0, sj0 = 0;
        if (tid < 128) {
            int b = tid >> 5, u = tid & 31;
            int u4 = u >> 2, cp = (u >> 1) & 1, half = u & 1;
            float gate[5];
#pragma unroll
            for (int g = 0; g < 5; g++) {
                float s = 0.f;
#pragma unroll
                for (int kb = 0; kb < 4; kb++) {
                    ull v = redk[(size_t)((kb * 5 + g) * 8 + u4) * 8 + b * 2 + cp];
                    s += half ? hi32(v) : lo32(v);
                }
                gate[g] = s + bcs[g * 32 + u];
            }
            int gb = gb0 + b, h = r * 32 + u;
            float cl = clcr[(b * 2 + 0) * 32 + u];
            float cr = clcr[(b * 2 + 1) * 32 + u];
            float cc = sigf(gate[1]) * cl + sigf(gate[2]) * cr + sigf(gate[0]) * tanhf(gate[4]);
            float hp = sigf(gate[3]) * tanhf(cc);
            g_states[gb][fsl[b]][h]     = cc;
            g_states[gb][fsl[b]][H + h] = hp;
            unsigned la = smem_u32(&hM[b * 256 + h]);
#pragma unroll
            for (int rr = 0; rr < CL; rr++) stc_f32(la, rr, hp);
        } else if (tid < 128 + NB * 96) {
            int ii0 = tid - 128;
            sb0 = ii0 / 96; sj0 = ii0 - sb0 * 96;
            int idx = selidx[sb0];
            if (sj0 >= idx + 1 && sj0 <= n - 2) { spv0 = pmi[sb0 * 96 + sj0 + 1]; swp0 = 1; }
            if (sj0 >= idx + 1 && sj0 <= n - 3) { slv0 = lg[sb0 * 96 + sj0 + 1]; swl0 = 1; }
        }
        __syncthreads();
        if (swp0) pmi[sb0 * 96 + sj0] = spv0;
        if (swl0) lg[sb0 * 96 + sj0] = slv0;
        if (tid < NB) pmi[tid * 96 + selidx[tid]] = fsl[tid];
        cluster_bar();                                   // SYNC1: hM visible

        // ---- xp pack: pure smem ----
        for (int i = tid; i < NB * 128; i += TPB) {
            int b = i >> 7, k = (i & 127) << 2;
            int idx = selidx[b];
            bool vA = (idx >= 1);
            bool vB = (idx <= n - 3);
            float4 a4, b4;
            if (k < H) {
                a4 = vA ? *(const float4*)&xnl[b * 256 + k] : make_float4(0.f, 0.f, 0.f, 0.f);
                b4 = vB ? *(const float4*)&hM[b * 256 + k]  : make_float4(0.f, 0.f, 0.f, 0.f);
            } else {
                a4 = vA ? *(const float4*)&hM[b * 256 + (k - H)]  : make_float4(0.f, 0.f, 0.f, 0.f);
                b4 = vB ? *(const float4*)&xnr[b * 256 + (k - H)] : make_float4(0.f, 0.f, 0.f, 0.f);
            }
            xp[b * 512 + k]     = pack2(a4.x, b4.x);
            xp[b * 512 + k + 1] = pack2(a4.y, b4.y);
            xp[b * 512 + k + 2] = pack2(a4.z, b4.z);
            xp[b * 512 + k + 3] = pack2(a4.w, b4.w);
        }
        __syncthreads();

        // ---- phase5 partials: 16j x 4b x 8 k-slices ----
        if (tid < 512) {
            int kh = tid >> 6, rest = tid & 63;
            int b = rest >> 4, j16 = rest & 15;
            const float* wr = Ws1s + j16 * 524 + kh * 64;
            const ull*   xr = xp + b * 512 + kh * 64;
            ull a0 = 0ull, a1 = 0ull;
#pragma unroll 8
            for (int m = 0; m < 16; m++) {
                float4 wv = *(const float4*)(wr + m * 4);
                ulonglong2 x01 = *(const ulonglong2*)(xr + m * 4);
                ulonglong2 x23 = *(const ulonglong2*)(xr + m * 4 + 2);
                a0 = fma2(pack2(wv.x, wv.x), x01.x, a0);
                a1 = fma2(pack2(wv.y, wv.y), x01.y, a1);
                a0 = fma2(pack2(wv.z, wv.z), x23.x, a0);
                a1 = fma2(pack2(wv.w, wv.w), x23.y, a1);
            }
            p5q[tid] = add2(a0, a1);
        }
        __syncthreads();
        if (tid < 64) {
            int j16 = tid & 15, b = tid >> 4;
            ull v = p5q[tid];
#pragma unroll
            for (int kh = 1; kh < 8; kh++) v = add2(v, p5q[kh * 64 + tid]);
            float sA = lo32(v) + bs1s[j16], sB = hi32(v) + bs1s[j16];
            float yA = tanhf(sA) * ws2s[j16];
            float yB = tanhf(sB) * ws2s[j16];
#pragma unroll
            for (int o = 1; o < 16; o <<= 1) {
                yA += __shfl_xor_sync(0xffffffffu, yA, o);
                yB += __shfl_xor_sync(0xffffffffu, yB, o);
            }
            if (j16 == 0) {
                unsigned laA = smem_u32(&p5a[r * 8 + b * 2 + 0]);
                unsigned laB = smem_u32(&p5a[r * 8 + b * 2 + 1]);
#pragma unroll
                for (int rr = 0; rr < CL; rr++) { stc_f32(laA, rr, yA); stc_f32(laB, rr, yB); }
            }
        }
        cluster_bar();                                   // SYNC2: p5a visible

        // ---- lg update (ordered rank sum) ----
        if (tid < 2 * NB) {
            int b = tid >> 1, s = tid & 1;
            int q = selidx[b] - 1 + s;
            if (q >= 0 && q <= n - 3) {
                float v = bs2v;
#pragma unroll
                for (int rr = 0; rr < CL; rr++) v += p5a[rr * 8 + b * 2 + s];
                lg[b * 96 + q] = v;
            }
        }
        __syncthreads();
    }

    // ---- root hidden ----
    if (tid < 128) {
        int b = tid >> 5, u = tid & 31;
        g_hroot[gb0 + b][r * 32 + u] = __ldcg(&g_states[gb0 + b][pmi[b * 96]][H + r * 32 + u]);
    }
}

// ======================================================================
__global__ void mlp_l1(const float* __restrict__ Wm1, const float* __restrict__ bm1) {
    __shared__ float hsh[H];
    int b = blockIdx.y, c = blockIdx.x * 256 + threadIdx.x;
    if (threadIdx.x < H) hsh[threadIdx.x] = g_hroot[b][threadIdx.x];
    __syncthreads();
    float acc = bm1[c];
    const float* wp = Wm1 + c;
#pragma unroll 8
    for (int k = 0; k < H; k++) acc = __fmaf_rn(hsh[k], wp[k * MLPD], acc);
    g_x1[b][c] = fmaxf(acc, 0.0f);
}

__global__ void mlp_l2(const float* __restrict__ Wm2, const float* __restrict__ bm2) {
    __shared__ float x1s[MLPD];
    int b = blockIdx.y, c = blockIdx.x * 256 + threadIdx.x;
    for (int i = threadIdx.x; i < MLPD; i += 256) x1s[i] = g_x1[b][i];
    __syncthreads();
    float acc = bm2[c];
    const float* wp = Wm2 + c;
#pragma unroll 8
    for (int k = 0; k < MLPD; k++) acc = __fmaf_rn(x1s[k], wp[k * MLPD], acc);
    g_x2[b][c] = fmaxf(acc, 0.0f);
}

__global__ void mlp_l3(const float* __restrict__ Wout, const float* __restrict__ bout,
                       float* __restrict__ out) {
    __shared__ float red[4][NC];
    int b = blockIdx.x, tid = threadIdx.x;
    float p0 = 0.f, p1 = 0.f, p2 = 0.f;
    for (int k = tid; k < MLPD; k += 128) {
        float xv = g_x2[b][k];
        p0 = __fmaf_rn(xv, Wout[k * NC + 0], p0);
        p1 = __fmaf_rn(xv, Wout[k * NC + 1], p1);
        p2 = __fmaf_rn(xv, Wout[k * NC + 2], p2);
    }
    for (int o = 16; o; o >>= 1) {
        p0 += __shfl_xor_sync(0xffffffffu, p0, o);
        p1 += __shfl_xor_sync(0xffffffffu, p1, o);
        p2 += __shfl_xor_sync(0xffffffffu, p2, o);
    }
    int lane = tid & 31, wrp = tid >> 5;
    if (lane == 0) { red[wrp][0] = p0; red[wrp][1] = p1; red[wrp][2] = p2; }
    __syncthreads();
    if (tid < NC) {
        float s = bout[tid];
        for (int w = 0; w < 4; w++) s += red[w][tid];
        out[b * NC + tid] = s;
    }
}

// ======================================================================
extern "C" void kernel_launch(void* const* d_in, const int* in_sizes, int n_in,
                              void* d_out, int out_size) {
    const int*   sent = (const int*)d_in[0];
    const float* emb  = (const float*)d_in[2];
    const float* Wenc = (const float*)d_in[3];
    const float* benc = (const float*)d_in[4];
    const float* Wc   = (const float*)d_in[5];
    const float* bc   = (const float*)d_in[6];
    const float* Ws1  = (const float*)d_in[7];
    const float* bs1  = (const float*)d_in[8];
    const float* Ws2  = (const float*)d_in[9];
    const float* bs2  = (const float*)d_in[10];
    const float* Wm1  = (const float*)d_in[11];
    const float* bm1  = (const float*)d_in[12];
    const float* Wm2  = (const float*)d_in[13];
    const float* bm2  = (const float*)d_in[14];
    const float* Wout = (const float*)d_in[15];
    const float* bout = (const float*)d_in[16];

    static int smem_set = 0;
    if (!smem_set) {
        cudaFuncSetAttribute(scan_kernel, cudaFuncAttributeMaxDynamicSharedMemorySize, SMEM_SZ);
        smem_set = 1;
    }

    prof_pad_kernel<<<1, 32>>>();   // keeps ncu's profiled slot on scan_kernel
    encode_kernel<<<768, 128>>>(sent, emb, Wenc, benc);
    initsel_kernel<<<dim3(6, 64), 128>>>(Ws1, bs1, Ws2, bs2);
    scan_kernel<<<NCL * CL, TPB, SMEM_SZ>>>(Wc, bc, Ws1, bs1, Ws2, bs2);
    mlp_l1<<<dim3(4, B), 256>>>(Wm1, bm1);
    mlp_l2<<<dim3(4, B), 256>>>(Wm2, bm2);
    mlp_l3<<<B, 128>>>(Wout, bout, (float*)d_out);
}

// round 12
// speedup vs baseline: 1.3841x; 1.3841x over previous
#include <cuda_runtime.h>
#include <math.h>

#define B   64
#define S   96
#define E   300
#define H   256
#define D   512
#define SEL 128
#define G5  1280
#define MLPD 1024
#define NC  3

#define CLG 16     // CTAs per group
#define NGR 8      // groups
#define NB  8      // batches per group
#define TPB 640
#define NS  97     // S + 1 spare slot

typedef unsigned long long ull;

__device__ __align__(16) float g_states[B][NS][D];
__device__ float g_logits0[B][S - 1];
__device__ float g_hroot[B][H];
__device__ float g_x1[B][MLPD];
__device__ float g_x2[B][MLPD];
__device__ float g_p5[B][2][CLG];
__device__ unsigned g_cnt[NGR];    // zero at load; reset by kernel epilogue
__device__ unsigned g_done[NGR];

__device__ __forceinline__ float sigf(float x) { return 1.0f / (1.0f + expf(-x)); }
__device__ __forceinline__ ull fma2(ull a, ull b, ull c) {
    ull d; asm("fma.rn.f32x2 %0, %1, %2, %3;" : "=l"(d) : "l"(a), "l"(b), "l"(c)); return d;
}
__device__ __forceinline__ ull add2(ull a, ull b) {
    ull d; asm("add.rn.f32x2 %0, %1, %2;" : "=l"(d) : "l"(a), "l"(b)); return d;
}
__device__ __forceinline__ ull pack2(float x, float y) {
    ull d; asm("mov.b64 %0, {%1, %2};" : "=l"(d) : "f"(x), "f"(y)); return d;
}
__device__ __forceinline__ float lo32(ull v) { return __uint_as_float((unsigned)v); }
__device__ __forceinline__ float hi32(ull v) { return __uint_as_float((unsigned)(v >> 32)); }

// ---- dynamic smem layout (bytes) ----
#define O_W     0        // float Wsm[512][84] (pad 84)   172032
#define O_XS2   172032   // ull  xs2[4][512]              16384
#define O_WS1S  188416   // float Ws1s[512][8]            16384
#define O_REDK  204800   // ull  redk[80][16]             10240
#define O_P5Q   215040   // float p5q[512][2]             4096
#define O_LG    219136   // float lg[8][96]               3072
#define O_PM    222208   // int  pm[8][96]                3072
#define O_CLCR  225280   // float clcr[8][2][16]          1024
#define O_BCS   226304   // float bcs[80]                 384
#define O_MISC  226688   // ints/floats                   512
#define SMEM_SZ 227328

__global__ void prof_pad_kernel() {}

// ======================================================================
__global__ void encode_kernel(const int* __restrict__ sent, const float* __restrict__ emb,
                              const float* __restrict__ Wenc, const float* __restrict__ benc) {
    __shared__ float xsh[8][E];
    __shared__ int tok[8];
    int row0 = blockIdx.x * 8, tid = threadIdx.x;
    if (tid < 8) tok[tid] = sent[row0 + tid];
    __syncthreads();
    for (int i = tid; i < 8 * E; i += 128) {
        int r = i / E, k = i - r * E;
        xsh[r][k] = emb[(long)tok[r] * E + k];
    }
    __syncthreads();
    int c = tid * 4;
    float4 acc[8];
#pragma unroll
    for (int r = 0; r < 8; r++) acc[r] = make_float4(0.f, 0.f, 0.f, 0.f);
    for (int k = 0; k < E; k++) {
        float4 w = *(const float4*)&Wenc[k * D + c];
#pragma unroll
        for (int r = 0; r < 8; r++) {
            float xv = xsh[r][k];
            acc[r].x = __fmaf_rn(xv, w.x, acc[r].x); acc[r].y = __fmaf_rn(xv, w.y, acc[r].y);
            acc[r].z = __fmaf_rn(xv, w.z, acc[r].z); acc[r].w = __fmaf_rn(xv, w.w, acc[r].w);
        }
    }
    float4 bv = *(const float4*)&benc[c];
#pragma unroll
    for (int r = 0; r < 8; r++) {
        acc[r].x += bv.x; acc[r].y += bv.y; acc[r].z += bv.z; acc[r].w += bv.w;
        int gr = row0 + r, b = gr / S, s = gr - b * S;
        *(float4*)&g_states[b][s][c] = acc[r];
    }
}

// ======================================================================
__global__ void initsel_kernel(const float* __restrict__ Ws1, const float* __restrict__ bs1,
                               const float* __restrict__ Ws2, const float* __restrict__ bs2) {
    __shared__ float hs[17][H];
    __shared__ float red[4];
    int b = blockIdx.y, p0 = blockIdx.x * 16, tid = threadIdx.x;
    int nrows = min(17, S - p0);
    for (int i = tid; i < nrows * H; i += 128) {
        int r = i >> 8, k = i & (H - 1);
        hs[r][k] = g_states[b][p0 + r][H + k];
    }
    __syncthreads();
    int npairs = min(16, (S - 1) - p0);
    for (int p = 0; p < npairs; p++) {
        float a[8];
#pragma unroll
        for (int m = 0; m < 8; m++) a[m] = 0.0f;
        const float* wp = Ws1 + tid;
        for (int k = 0; k < 64; k++) {
#pragma unroll
            for (int m = 0; m < 4; m++)
                a[m] = __fmaf_rn(hs[p][m * 64 + k], wp[(m * 64 + k) * SEL], a[m]);
#pragma unroll
            for (int m = 0; m < 4; m++)
                a[4 + m] = __fmaf_rn(hs[p + 1][m * 64 + k], wp[(256 + m * 64 + k) * SEL], a[4 + m]);
        }
        float s = a[0] + a[1] + a[2] + a[3] + a[4] + a[5] + a[6] + a[7] + bs1[tid];
        float y = tanhf(s) * Ws2[tid];
        for (int o = 16; o; o >>= 1) y += __shfl_xor_sync(0xffffffffu, y, o);
        if ((tid & 31) == 0) red[tid >> 5] = y;
        __syncthreads();
        if (tid == 0) g_logits0[b][p0 + p] = red[0] + red[1] + red[2] + red[3] + bs2[0];
        __syncthreads();
    }
}

// ======================================================================
// Persistent scan: 128 CTAs = 8 groups x 16. Group owns 8 batches.
// CTA r: gate cols h in [16r,16r+16); sel j in [8r,8r+8).
// Full W_comp slice cached in SMEM. Group sync via L2 spin barrier.
// ======================================================================
__global__ void __launch_bounds__(TPB, 1)
scan_kernel(const float* __restrict__ Wc,  const float* __restrict__ bc,
            const float* __restrict__ Ws1, const float* __restrict__ bs1,
            const float* __restrict__ Ws2, const float* __restrict__ bs2) {
    extern __shared__ char dsm[];
    float* Wsm  = (float*)(dsm + O_W);      // [512][84] (80 used)
    ull*   xs2  = (ull*)(dsm + O_XS2);      // [4 pairs][512] (x_b0, x_b1)
    float* Ws1s = (float*)(dsm + O_WS1S);   // [512][8]
    ull*   redk = (ull*)(dsm + O_REDK);     // [80 rowquads][16]
    float* p5q  = (float*)(dsm + O_P5Q);    // [512][2]
    float* lg   = (float*)(dsm + O_LG);
    int*   pmi  = (int*)(dsm + O_PM);
    float* clcr = (float*)(dsm + O_CLCR);   // [8][2][16]
    float* bcs  = (float*)(dsm + O_BCS);    // [80] (g*16+u)
    int*   misc = (int*)(dsm + O_MISC);
    int* selidx = misc;       int* sLa = misc + 8;  int* sRa = misc + 16;
    int* frs    = misc + 24;  int* fsl = misc + 32;
    float* bs1s = (float*)(misc + 40);      // [8]
    float* ws2s = (float*)(misc + 48);      // [8]

    int tid = threadIdx.x;
    int r   = blockIdx.x & (CLG - 1);
    int gq  = blockIdx.x >> 4;
    int gb0 = gq * NB;

    // ---- one-time preloads ----
    for (int i = tid; i < 512 * 20; i += TPB) {     // W_comp slice
        int k = i / 20, q = i - k * 20;             // q = col-quad (g*4+cq)
        int g = q >> 2, u4 = (q & 3) * 4;
        float4 w = *(const float4*)&Wc[(size_t)k * G5 + g * 256 + r * 16 + u4];
        *(float4*)&Wsm[k * 84 + q * 4] = w;
    }
    for (int i = tid; i < 512 * 8; i += TPB) {      // W_sel1 j-slice
        int k = i >> 3, j = i & 7;
        Ws1s[k * 8 + j] = Ws1[(size_t)k * SEL + r * 8 + j];
    }
    if (tid < 80) {
        int g = tid >> 4, u = tid & 15;
        bcs[tid] = bc[g * 256 + r * 16 + u];
    }
    if (tid < 8) { bs1s[tid] = bs1[r * 8 + tid]; ws2s[tid] = Ws2[r * 8 + tid]; frs[tid] = 96; }
    for (int i = tid; i < NB * (S - 1); i += TPB) {
        int b = i / (S - 1), j = i - b * (S - 1);
        lg[b * 96 + j] = g_logits0[gb0 + b][j];
    }
    for (int i = tid; i < NB * S; i += TPB) {
        int b = i / S, j = i - b * S;
        pmi[b * 96 + j] = j;
    }
    float bs2v = bs2[0];
    __syncthreads();

    // compose geometry: 20 warps = cg(5) x ckb(4); lane = cks(8)*4 + cq(4)
    int wid = tid >> 5, lane = tid & 31;
    int cg  = wid % 5, ckb = wid / 5;
    int cks = lane >> 2, cq = lane & 3;
    int wbase = cg * 16 + cq * 4;

    unsigned tgt = 0;

    for (int t = 0; t < S - 1; t++) {
        int n = S - t, np = n - 1;

        // ---- argmax (replicated): 8 batches x 32 lanes ----
        if (tid < 256) {
            int b = tid >> 5, ln = tid & 31;
            float best = -1e30f; int bi = 0;
            for (int j = ln; j < np; j += 32) {
                float v = lg[b * 96 + j];
                if (v > best) { best = v; bi = j; }
            }
            for (int o = 16; o; o >>= 1) {
                float ov = __shfl_xor_sync(0xffffffffu, best, o);
                int   oi = __shfl_xor_sync(0xffffffffu, bi, o);
                if (ov > best || (ov == best && oi < bi)) { best = ov; bi = oi; }
            }
            if (ln == 0) {
                int sl = pmi[b * 96 + bi], sr = pmi[b * 96 + bi + 1];
                selidx[b] = bi; sLa[b] = sl; sRa[b] = sr;
                fsl[b] = frs[b];
                frs[b] = sr;
            }
        }
        __syncthreads();

        // ---- staging: xs2 (pair-packed) + clcr prefetch ----
        if (tid < 512) {
            int p = tid >> 7, kq = (tid & 127) << 2;
            int b0 = 2 * p, b1 = 2 * p + 1;
            int slot0 = (kq < H) ? sLa[b0] : sRa[b0];
            int slot1 = (kq < H) ? sLa[b1] : sRa[b1];
            int col = (kq < H) ? (H + kq) : kq;
            float4 a = __ldcg((const float4*)&g_states[gb0 + b0][slot0][col]);
            float4 c = __ldcg((const float4*)&g_states[gb0 + b1][slot1][col]);
            xs2[p * 512 + kq]     = pack2(a.x, c.x);
            xs2[p * 512 + kq + 1] = pack2(a.y, c.y);
            xs2[p * 512 + kq + 2] = pack2(a.z, c.z);
            xs2[p * 512 + kq + 3] = pack2(a.w, c.w);
        } else if (tid < 512 + 256) {
            int i2 = tid - 512;   // only 256 of 128 remaining... split below
            (void)i2;
        }
        if (tid < 256) {
            // clcr done after xs2 pass by same low threads next sync; fold here:
        }
        __syncthreads();
        if (tid < 256) {
            int b = tid >> 5, half = (tid >> 4) & 1, u = tid & 15;
            clcr[(b * 2 + half) * 16 + u] =
                __ldcg(&g_states[gb0 + b][half ? sRa[b] : sLa[b]][r * 16 + u]);
        }
        __syncthreads();

        // ---- compose from SMEM weights ----
        {
            ull acc[16];   // [c(4)][pair(4)]
#pragma unroll
            for (int i = 0; i < 16; i++) acc[i] = 0ull;
#pragma unroll 4
            for (int m = 0; m < 16; m++) {
                int k = ckb * 128 + m * 8 + cks;
                float4 w4 = *(const float4*)&Wsm[k * 84 + wbase];
                ull x0 = xs2[k], x1 = xs2[512 + k], x2 = xs2[1024 + k], x3 = xs2[1536 + k];
                ull w;
                w = pack2(w4.x, w4.x);
                acc[0] = fma2(w, x0, acc[0]); acc[1] = fma2(w, x1, acc[1]);
                acc[2] = fma2(w, x2, acc[2]); acc[3] = fma2(w, x3, acc[3]);
                w = pack2(w4.y, w4.y);
                acc[4] = fma2(w, x0, acc[4]); acc[5] = fma2(w, x1, acc[5]);
                acc[6] = fma2(w, x2, acc[6]); acc[7] = fma2(w, x3, acc[7]);
                w = pack2(w4.z, w4.z);
                acc[8] = fma2(w, x0, acc[8]); acc[9] = fma2(w, x1, acc[9]);
                acc[10] = fma2(w, x2, acc[10]); acc[11] = fma2(w, x3, acc[11]);
                w = pack2(w4.w, w4.w);
                acc[12] = fma2(w, x0, acc[12]); acc[13] = fma2(w, x1, acc[13]);
                acc[14] = fma2(w, x2, acc[14]); acc[15] = fma2(w, x3, acc[15]);
            }
#pragma unroll
            for (int i = 0; i < 16; i++) {   // reduce over cks (lane bits 2,3,4)
                acc[i] = add2(acc[i], __shfl_xor_sync(0xffffffffu, acc[i], 4));
                acc[i] = add2(acc[i], __shfl_xor_sync(0xffffffffu, acc[i], 8));
                acc[i] = add2(acc[i], __shfl_xor_sync(0xffffffffu, acc[i], 16));
            }
            if (cks == 0) {
                ull* dst = &redk[(size_t)((ckb * 5 + cg) * 4 + cq) * 16];
#pragma unroll
                for (int i = 0; i < 16; i++) dst[i] = acc[i];
            }
        }
        __syncthreads();

        // ---- gates (tid<128) overlapped with shift-read (tid>=128) ----
        int spv0 = 0, swp0 = 0, swl0 = 0; float slv0 = 0.f; int sb0 = 0, sj0 = 0;
        int spv1 = 0, swp1 = 0, swl1 = 0; float slv1 = 0.f; int sb1 = 0, sj1 = 0;
        if (tid < 128) {
            int b = tid >> 4, u = tid & 15;
            int ucq = u >> 2, uc = u & 3, p = b >> 1, half = b & 1;
            float gate[5];
#pragma unroll
            for (int g = 0; g < 5; g++) {
                float s = 0.f;
#pragma unroll
                for (int kb = 0; kb < 4; kb++) {
                    ull v = redk[(size_t)((kb * 5 + g) * 4 + ucq) * 16 + uc * 4 + p];
                    s += half ? hi32(v) : lo32(v);
                }
                gate[g] = s + bcs[g * 16 + u];
            }
            int gb = gb0 + b, h = r * 16 + u;
            float cl = clcr[(b * 2 + 0) * 16 + u];
            float cr = clcr[(b * 2 + 1) * 16 + u];
            float cc = sigf(gate[1]) * cl + sigf(gate[2]) * cr + sigf(gate[0]) * tanhf(gate[4]);
            float hp = sigf(gate[3]) * tanhf(cc);
            g_states[gb][fsl[b]][h]     = cc;
            g_states[gb][fsl[b]][H + h] = hp;
        } else {
            int ii0 = tid - 128, ii1 = ii0 + 512;
            sb0 = ii0 / 96; sj0 = ii0 - sb0 * 96;
            {
                int idx = selidx[sb0];
                if (sj0 >= idx + 1 && sj0 <= n - 2) { spv0 = pmi[sb0 * 96 + sj0 + 1]; swp0 = 1; }
                if (sj0 >= idx + 1 && sj0 <= n - 3) { slv0 = lg[sb0 * 96 + sj0 + 1]; swl0 = 1; }
            }
            if (ii1 < NB * 96) {
                sb1 = ii1 / 96; sj1 = ii1 - sb1 * 96;
                int idx = selidx[sb1];
                if (sj1 >= idx + 1 && sj1 <= n - 2) { spv1 = pmi[sb1 * 96 + sj1 + 1]; swp1 = 1; }
                if (sj1 >= idx + 1 && sj1 <= n - 3) { slv1 = lg[sb1 * 96 + sj1 + 1]; swl1 = 1; }
            }
        }
        __syncthreads();
        if (tid >= 128) {
            if (swp0) pmi[sb0 * 96 + sj0] = spv0;
            if (swl0) lg[sb0 * 96 + sj0] = slv0;
            if (swp1) pmi[sb1 * 96 + sj1] = spv1;
            if (swl1) lg[sb1 * 96 + sj1] = slv1;
        }
        if (tid < NB) pmi[tid * 96 + selidx[tid]] = fsl[tid];

        // ---- SYNC1: fresh states visible group-wide ----
        __syncthreads();
        tgt += CLG;
        if (tid == 0) {
            __threadfence();
            atomicAdd(&g_cnt[gq], 1u);
            while (atomicAdd(&g_cnt[gq], 0u) < tgt) {}
            __threadfence();
        }
        __syncthreads();

        // ---- phase5: own j-slice, 8 batches, both pairs; x from L2 ----
        if (tid < 512) {
            int ks = tid >> 6, bj = tid & 63;
            int b = bj >> 3, j = bj & 7;
            int gb = gb0 + b;
            int idx = selidx[b];
            int q0 = (idx >= 1) ? (idx - 1) : 0;
            int base = ks * 64;
            const float* xA; const float* xB;
            if (base < H) {
                xA = &g_states[gb][pmi[b * 96 + q0]][H + base];
                xB = &g_states[gb][pmi[b * 96 + idx]][H + base];
            } else {
                xA = &g_states[gb][pmi[b * 96 + q0 + 1]][base];
                xB = &g_states[gb][pmi[b * 96 + idx + 1]][base];
            }
            const float* wr = Ws1s + base * 8 + j;
            float accA = 0.f, accB = 0.f;
#pragma unroll 4
            for (int mm = 0; mm < 64; mm += 4) {
                float4 xa = __ldcg((const float4*)(xA + mm));
                float4 xb = __ldcg((const float4*)(xB + mm));
                float w0 = wr[(mm + 0) * 8], w1 = wr[(mm + 1) * 8];
                float w2 = wr[(mm + 2) * 8], w3 = wr[(mm + 3) * 8];
                accA = __fmaf_rn(xa.x, w0, accA); accB = __fmaf_rn(xb.x, w0, accB);
                accA = __fmaf_rn(xa.y, w1, accA); accB = __fmaf_rn(xb.y, w1, accB);
                accA = __fmaf_rn(xa.z, w2, accA); accB = __fmaf_rn(xb.z, w2, accB);
                accA = __fmaf_rn(xa.w, w3, accA); accB = __fmaf_rn(xb.w, w3, accB);
            }
            p5q[tid * 2]     = accA;
            p5q[tid * 2 + 1] = accB;
        }
        __syncthreads();
        if (tid < 64) {
            int b = tid >> 3, j = tid & 7;
            float sA = 0.f, sB = 0.f;
#pragma unroll
            for (int ks = 0; ks < 8; ks++) {
                sA += p5q[(ks * 64 + tid) * 2];
                sB += p5q[(ks * 64 + tid) * 2 + 1];
            }
            float yA = tanhf(sA + bs1s[j]) * ws2s[j];
            float yB = tanhf(sB + bs1s[j]) * ws2s[j];
#pragma unroll
            for (int o = 1; o < 8; o <<= 1) {
                yA += __shfl_xor_sync(0xffffffffu, yA, o);
                yB += __shfl_xor_sync(0xffffffffu, yB, o);
            }
            if (j == 0) { g_p5[gb0 + b][0][r] = yA; g_p5[gb0 + b][1][r] = yB; }
        }

        // ---- SYNC2: p5 partials visible ----
        __syncthreads();
        tgt += CLG;
        if (tid == 0) {
            __threadfence();
            atomicAdd(&g_cnt[gq], 1u);
            while (atomicAdd(&g_cnt[gq], 0u) < tgt) {}
            __threadfence();
        }
        __syncthreads();

        // ---- lg update (ordered rank sum over 16) ----
        if (tid < 2 * NB) {
            int b = tid >> 1, s = tid & 1;
            int q = selidx[b] - 1 + s;
            if (q >= 0 && q <= n - 3) {
                float v = bs2v;
#pragma unroll
                for (int rr = 0; rr < CLG; rr++) v += __ldcg(&g_p5[gb0 + b][s][rr]);
                lg[b * 96 + q] = v;
            }
        }
        __syncthreads();
    }

    // ---- root hidden: own h-slice, 8 batches ----
    if (tid < 128) {
        int b = tid >> 4, u = tid & 15;
        g_hroot[gb0 + b][r * 16 + u] =
            __ldcg(&g_states[gb0 + b][pmi[b * 96]][H + r * 16 + u]);
    }

    // ---- reset barrier counters for the next graph replay ----
    __syncthreads();
    if (tid == 0) {
        __threadfence();
        atomicAdd(&g_done[gq], 1u);
        if (r == 0) {
            while (atomicAdd(&g_done[gq], 0u) < CLG) {}
            g_cnt[gq] = 0u;
            g_done[gq] = 0u;
            __threadfence();
        }
    }
}

// ======================================================================
__global__ void mlp_l1(const float* __restrict__ Wm1, const float* __restrict__ bm1) {
    __shared__ float hsh[H];
    int b = blockIdx.y, c = blockIdx.x * 256 + threadIdx.x;
    if (threadIdx.x < H) hsh[threadIdx.x] = g_hroot[b][threadIdx.x];
    __syncthreads();
    float acc = bm1[c];
    const float* wp = Wm1 + c;
#pragma unroll 8
    for (int k = 0; k < H; k++) acc = __fmaf_rn(hsh[k], wp[k * MLPD], acc);
    g_x1[b][c] = fmaxf(acc, 0.0f);
}

__global__ void mlp_l2(const float* __restrict__ Wm2, const float* __restrict__ bm2) {
    __shared__ float x1s[MLPD];
    int b = blockIdx.y, c = blockIdx.x * 256 + threadIdx.x;
    for (int i = threadIdx.x; i < MLPD; i += 256) x1s[i] = g_x1[b][i];
    __syncthreads();
    float acc = bm2[c];
    const float* wp = Wm2 + c;
#pragma unroll 8
    for (int k = 0; k < MLPD; k++) acc = __fmaf_rn(x1s[k], wp[k * MLPD], acc);
    g_x2[b][c] = fmaxf(acc, 0.0f);
}

__global__ void mlp_l3(const float* __restrict__ Wout, const float* __restrict__ bout,
                       float* __restrict__ out) {
    __shared__ float red[4][NC];
    int b = blockIdx.x, tid = threadIdx.x;
    float p0 = 0.f, p1 = 0.f, p2 = 0.f;
    for (int k = tid; k < MLPD; k += 128) {
        float xv = g_x2[b][k];
        p0 = __fmaf_rn(xv, Wout[k * NC + 0], p0);
        p1 = __fmaf_rn(xv, Wout[k * NC + 1], p1);
        p2 = __fmaf_rn(xv, Wout[k * NC + 2], p2);
    }
    for (int o = 16; o; o >>= 1) {
        p0 += __shfl_xor_sync(0xffffffffu, p0, o);
        p1 += __shfl_xor_sync(0xffffffffu, p1, o);
        p2 += __shfl_xor_sync(0xffffffffu, p2, o);
    }
    int lane = tid & 31, wrp = tid >> 5;
    if (lane == 0) { red[wrp][0] = p0; red[wrp][1] = p1; red[wrp][2] = p2; }
    __syncthreads();
    if (tid < NC) {
        float s = bout[tid];
        for (int w = 0; w < 4; w++) s += red[w][tid];
        out[b * NC + tid] = s;
    }
}

// ======================================================================
extern "C" void kernel_launch(void* const* d_in, const int* in_sizes, int n_in,
                              void* d_out, int out_size) {
    const int*   sent = (const int*)d_in[0];
    const float* emb  = (const float*)d_in[2];
    const float* Wenc = (const float*)d_in[3];
    const float* benc = (const float*)d_in[4];
    const float* Wc   = (const float*)d_in[5];
    const float* bc   = (const float*)d_in[6];
    const float* Ws1  = (const float*)d_in[7];
    const float* bs1  = (const float*)d_in[8];
    const float* Ws2  = (const float*)d_in[9];
    const float* bs2  = (const float*)d_in[10];
    const float* Wm1  = (const float*)d_in[11];
    const float* bm1  = (const float*)d_in[12];
    const float* Wm2  = (const float*)d_in[13];
    const float* bm2  = (const float*)d_in[14];
    const float* Wout = (const float*)d_in[15];
    const float* bout = (const float*)d_in[16];

    static int smem_set = 0;
    if (!smem_set) {
        cudaFuncSetAttribute(scan_kernel, cudaFuncAttributeMaxDynamicSharedMemorySize, SMEM_SZ);
        smem_set = 1;
    }

    prof_pad_kernel<<<1, 32>>>();   // keeps ncu's profiled slot on scan_kernel
    encode_kernel<<<768, 128>>>(sent, emb, Wenc, benc);
    initsel_kernel<<<dim3(6, 64), 128>>>(Ws1, bs1, Ws2, bs2);
    scan_kernel<<<NGR * CLG, TPB, SMEM_SZ>>>(Wc, bc, Ws1, bs1, Ws2, bs2);
    mlp_l1<<<dim3(4, B), 256>>>(Wm1, bm1);
    mlp_l2<<<dim3(4, B), 256>>>(Wm2, bm2);
    mlp_l3<<<B, 128>>>(Wout, bout, (float*)d_out);
}

// round 13
// speedup vs baseline: 1.6056x; 1.1601x over previous
#include <cuda_runtime.h>
#include <math.h>

#define B   64
#define S   96
#define E   300
#define H   256
#define D   512
#define SEL 128
#define G5  1280
#define MLPD 1024
#define NC  3

#define CLG 16     // CTAs per group
#define NGR 8      // groups
#define NB  8      // batches per group
#define TPB 640
#define NS  97     // S + 1 spare slot

typedef unsigned long long ull;

__device__ __align__(16) float g_states[B][NS][D];
__device__ float g_logits0[B][S - 1];
__device__ float g_hroot[B][H];
__device__ float g_x1[B][MLPD];
__device__ float g_x2[B][MLPD];
__device__ __align__(16) ull g_part[2][NGR][NB][CLG][SEL];  // double-buffered partial logits
__device__ unsigned g_cnt[NGR];    // zero at load; reset by epilogue
__device__ unsigned g_done[NGR];

__device__ __forceinline__ float sigf(float x) { return 1.0f / (1.0f + expf(-x)); }
__device__ __forceinline__ ull fma2(ull a, ull b, ull c) {
    ull d; asm("fma.rn.f32x2 %0, %1, %2, %3;" : "=l"(d) : "l"(a), "l"(b), "l"(c)); return d;
}
__device__ __forceinline__ ull add2(ull a, ull b) {
    ull d; asm("add.rn.f32x2 %0, %1, %2;" : "=l"(d) : "l"(a), "l"(b)); return d;
}
__device__ __forceinline__ ull pack2(float x, float y) {
    ull d; asm("mov.b64 %0, {%1, %2};" : "=l"(d) : "f"(x), "f"(y)); return d;
}
__device__ __forceinline__ float lo32(ull v) { return __uint_as_float((unsigned)v); }
__device__ __forceinline__ float hi32(ull v) { return __uint_as_float((unsigned)(v >> 32)); }

// ---- dynamic smem layout (bytes) ----
#define O_W     0        // float Wsm[512][84]            172032
#define O_XS2   172032   // ull  xs2[4][512]              16384
#define O_WS1A  188416   // float ws1a[16][128]           8192
#define O_WS1B  196608   // float ws1b[16][128]           8192
#define O_REDK  204800   // ull  redk[80][16]             10240
#define O_LG    215040   // float lg[8][96]               3072
#define O_PM    218112   // int  pm[8][96]                3072
#define O_CLCR  221184   // float clcr[8][2][16]          1024
#define O_BCS   222208   // float bcs[80]                 384
#define O_HLOC  222592   // float hloc[8][16]             512
#define O_LNB   223104   // float lnb[8][16]              512
#define O_RNB   223616   // float rnb[8][16]              512
#define O_BS1F  224128   // float bs1f[128]               512
#define O_WS2F  224640   // float ws2f[128]               512
#define O_RED   225152   // float red[8][2][2]            128
#define O_MISC  225280   // ints/floats                   512
#define SMEM_SZ 225792

__global__ void prof_pad_kernel() {}

// ======================================================================
__global__ void encode_kernel(const int* __restrict__ sent, const float* __restrict__ emb,
                              const float* __restrict__ Wenc, const float* __restrict__ benc) {
    __shared__ float xsh[8][E];
    __shared__ int tok[8];
    int row0 = blockIdx.x * 8, tid = threadIdx.x;
    if (tid < 8) tok[tid] = sent[row0 + tid];
    __syncthreads();
    for (int i = tid; i < 8 * E; i += 128) {
        int r = i / E, k = i - r * E;
        xsh[r][k] = emb[(long)tok[r] * E + k];
    }
    __syncthreads();
    int c = tid * 4;
    float4 acc[8];
#pragma unroll
    for (int r = 0; r < 8; r++) acc[r] = make_float4(0.f, 0.f, 0.f, 0.f);
    for (int k = 0; k < E; k++) {
        float4 w = *(const float4*)&Wenc[k * D + c];
#pragma unroll
        for (int r = 0; r < 8; r++) {
            float xv = xsh[r][k];
            acc[r].x = __fmaf_rn(xv, w.x, acc[r].x); acc[r].y = __fmaf_rn(xv, w.y, acc[r].y);
            acc[r].z = __fmaf_rn(xv, w.z, acc[r].z); acc[r].w = __fmaf_rn(xv, w.w, acc[r].w);
        }
    }
    float4 bv = *(const float4*)&benc[c];
#pragma unroll
    for (int r = 0; r < 8; r++) {
        acc[r].x += bv.x; acc[r].y += bv.y; acc[r].z += bv.z; acc[r].w += bv.w;
        int gr = row0 + r, b = gr / S, s = gr - b * S;
        *(float4*)&g_states[b][s][c] = acc[r];
    }
}

// ======================================================================
__global__ void initsel_kernel(const float* __restrict__ Ws1, const float* __restrict__ bs1,
                               const float* __restrict__ Ws2, const float* __restrict__ bs2) {
    __shared__ float hs[17][H];
    __shared__ float red[4];
    int b = blockIdx.y, p0 = blockIdx.x * 16, tid = threadIdx.x;
    int nrows = min(17, S - p0);
    for (int i = tid; i < nrows * H; i += 128) {
        int r = i >> 8, k = i & (H - 1);
        hs[r][k] = g_states[b][p0 + r][H + k];
    }
    __syncthreads();
    int npairs = min(16, (S - 1) - p0);
    for (int p = 0; p < npairs; p++) {
        float a[8];
#pragma unroll
        for (int m = 0; m < 8; m++) a[m] = 0.0f;
        const float* wp = Ws1 + tid;
        for (int k = 0; k < 64; k++) {
#pragma unroll
            for (int m = 0; m < 4; m++)
                a[m] = __fmaf_rn(hs[p][m * 64 + k], wp[(m * 64 + k) * SEL], a[m]);
#pragma unroll
            for (int m = 0; m < 4; m++)
                a[4 + m] = __fmaf_rn(hs[p + 1][m * 64 + k], wp[(256 + m * 64 + k) * SEL], a[4 + m]);
        }
        float s = a[0] + a[1] + a[2] + a[3] + a[4] + a[5] + a[6] + a[7] + bs1[tid];
        float y = tanhf(s) * Ws2[tid];
        for (int o = 16; o; o >>= 1) y += __shfl_xor_sync(0xffffffffu, y, o);
        if ((tid & 31) == 0) red[tid >> 5] = y;
        __syncthreads();
        if (tid == 0) g_logits0[b][p0 + p] = red[0] + red[1] + red[2] + red[3] + bs2[0];
        __syncthreads();
    }
}

// ======================================================================
// Persistent scan: 128 CTAs = 8 groups x 16, 8 batches/group.
// CTA r: gate cols h in [16r,16r+16); ONE group barrier per step.
// Phase-5 partials are k-sliced and fully local (own h' + pre-staged
// neighbors); logits reconstructed replicately after the barrier.
// ======================================================================
__global__ void __launch_bounds__(TPB, 1)
scan_kernel(const float* __restrict__ Wc,  const float* __restrict__ bc,
            const float* __restrict__ Ws1, const float* __restrict__ bs1,
            const float* __restrict__ Ws2, const float* __restrict__ bs2) {
    extern __shared__ char dsm[];
    float* Wsm  = (float*)(dsm + O_W);
    ull*   xs2  = (ull*)(dsm + O_XS2);
    float* ws1a = (float*)(dsm + O_WS1A);   // rows 16r+u
    float* ws1b = (float*)(dsm + O_WS1B);   // rows 256+16r+u
    ull*   redk = (ull*)(dsm + O_REDK);
    float* lg   = (float*)(dsm + O_LG);
    int*   pmi  = (int*)(dsm + O_PM);
    float* clcr = (float*)(dsm + O_CLCR);
    float* bcs  = (float*)(dsm + O_BCS);
    float* hloc = (float*)(dsm + O_HLOC);
    float* lnb  = (float*)(dsm + O_LNB);
    float* rnb  = (float*)(dsm + O_RNB);
    float* bs1f = (float*)(dsm + O_BS1F);
    float* ws2f = (float*)(dsm + O_WS2F);
    float* red  = (float*)(dsm + O_RED);    // [8][2][2]
    int*   misc = (int*)(dsm + O_MISC);
    int* selidx = misc;       int* sLa = misc + 8;  int* sRa = misc + 16;
    int* frs    = misc + 24;  int* fsl = misc + 32;

    int tid = threadIdx.x;
    int r   = blockIdx.x & (CLG - 1);
    int gq  = blockIdx.x >> 4;
    int gb0 = gq * NB;

    // ---- one-time preloads ----
    for (int i = tid; i < 512 * 20; i += TPB) {
        int k = i / 20, q = i - k * 20;
        int g = q >> 2, u4 = (q & 3) * 4;
        float4 w = *(const float4*)&Wc[(size_t)k * G5 + g * 256 + r * 16 + u4];
        *(float4*)&Wsm[k * 84 + q * 4] = w;
    }
    for (int i = tid; i < 2048; i += TPB) {
        int u = i >> 7, j = i & 127;
        ws1a[i] = Ws1[(size_t)(r * 16 + u) * SEL + j];
        ws1b[i] = Ws1[(size_t)(256 + r * 16 + u) * SEL + j];
    }
    if (tid < 128) { bs1f[tid] = bs1[tid]; ws2f[tid] = Ws2[tid]; }
    if (tid < 80) {
        int g = tid >> 4, u = tid & 15;
        bcs[tid] = bc[g * 256 + r * 16 + u];
    }
    if (tid < 8) frs[tid] = 96;
    for (int i = tid; i < NB * (S - 1); i += TPB) {
        int b = i / (S - 1), j = i - b * (S - 1);
        lg[b * 96 + j] = g_logits0[gb0 + b][j];
    }
    for (int i = tid; i < NB * S; i += TPB) {
        int b = i / S, j = i - b * S;
        pmi[b * 96 + j] = j;
    }
    float bs2v = bs2[0];
    __syncthreads();

    // compose geometry (as R12)
    int wid = tid >> 5, lane = tid & 31;
    int cg  = wid % 5, ckb = wid / 5;
    int cks = lane >> 2, cq = lane & 3;
    int wbase = cg * 16 + cq * 4;

    unsigned tgt = 0;

    for (int t = 0; t < S - 1; t++) {
        int n = S - t, np = n - 1;
        int par = t & 1;
        ull* gp = &g_part[par][gq][0][0][0];

        // ---- argmax (replicated) ----
        if (tid < 256) {
            int b = tid >> 5, ln = tid & 31;
            float best = -1e30f; int bi = 0;
            for (int j = ln; j < np; j += 32) {
                float v = lg[b * 96 + j];
                if (v > best) { best = v; bi = j; }
            }
            for (int o = 16; o; o >>= 1) {
                float ov = __shfl_xor_sync(0xffffffffu, best, o);
                int   oi = __shfl_xor_sync(0xffffffffu, bi, o);
                if (ov > best || (ov == best && oi < bi)) { best = ov; bi = oi; }
            }
            if (ln == 0) {
                int sl = pmi[b * 96 + bi], sr = pmi[b * 96 + bi + 1];
                selidx[b] = bi; sLa[b] = sl; sRa[b] = sr;
                fsl[b] = frs[b];
                frs[b] = sr;
            }
        }
        __syncthreads();

        // ---- staging: xs2 + clcr + neighbor slices ----
        if (tid < 512) {
            int p = tid >> 7, kq = (tid & 127) << 2;
            int b0 = 2 * p, b1 = 2 * p + 1;
            int slot0 = (kq < H) ? sLa[b0] : sRa[b0];
            int slot1 = (kq < H) ? sLa[b1] : sRa[b1];
            int col = (kq < H) ? (H + kq) : kq;
            float4 a = __ldcg((const float4*)&g_states[gb0 + b0][slot0][col]);
            float4 c = __ldcg((const float4*)&g_states[gb0 + b1][slot1][col]);
            xs2[p * 512 + kq]     = pack2(a.x, c.x);
            xs2[p * 512 + kq + 1] = pack2(a.y, c.y);
            xs2[p * 512 + kq + 2] = pack2(a.z, c.z);
            xs2[p * 512 + kq + 3] = pack2(a.w, c.w);
        } else {
            int i0 = (tid - 512) * 2;
#pragma unroll
            for (int s = 0; s < 2; s++) {
                int i = i0 + s;
                int b = i >> 5, half = (i >> 4) & 1, u = i & 15;
                clcr[(b * 2 + half) * 16 + u] =
                    __ldcg(&g_states[gb0 + b][half ? sRa[b] : sLa[b]][r * 16 + u]);
            }
        }
        if (tid < 256) {   // neighbor h slices for own 16 cols (old states)
            int b = tid >> 5, rest = tid & 31;
            int half = rest >> 4, u = rest & 15;
            int idx = selidx[b];
            float v = 0.f;
            if (half == 0) {
                if (idx >= 1)
                    v = __ldcg(&g_states[gb0 + b][pmi[b * 96 + idx - 1]][H + r * 16 + u]);
                lnb[b * 16 + u] = v;
            } else {
                if (idx <= n - 3)
                    v = __ldcg(&g_states[gb0 + b][pmi[b * 96 + idx + 2]][H + r * 16 + u]);
                rnb[b * 16 + u] = v;
            }
        }
        __syncthreads();

        // ---- compose from SMEM weights (as R12) ----
        {
            ull acc[16];
#pragma unroll
            for (int i = 0; i < 16; i++) acc[i] = 0ull;
#pragma unroll 4
            for (int m = 0; m < 16; m++) {
                int k = ckb * 128 + m * 8 + cks;
                float4 w4 = *(const float4*)&Wsm[k * 84 + wbase];
                ull x0 = xs2[k], x1 = xs2[512 + k], x2 = xs2[1024 + k], x3 = xs2[1536 + k];
                ull w;
                w = pack2(w4.x, w4.x);
                acc[0] = fma2(w, x0, acc[0]); acc[1] = fma2(w, x1, acc[1]);
                acc[2] = fma2(w, x2, acc[2]); acc[3] = fma2(w, x3, acc[3]);
                w = pack2(w4.y, w4.y);
                acc[4] = fma2(w, x0, acc[4]); acc[5] = fma2(w, x1, acc[5]);
                acc[6] = fma2(w, x2, acc[6]); acc[7] = fma2(w, x3, acc[7]);
                w = pack2(w4.z, w4.z);
                acc[8] = fma2(w, x0, acc[8]); acc[9] = fma2(w, x1, acc[9]);
                acc[10] = fma2(w, x2, acc[10]); acc[11] = fma2(w, x3, acc[11]);
                w = pack2(w4.w, w4.w);
                acc[12] = fma2(w, x0, acc[12]); acc[13] = fma2(w, x1, acc[13]);
                acc[14] = fma2(w, x2, acc[14]); acc[15] = fma2(w, x3, acc[15]);
            }
#pragma unroll
            for (int i = 0; i < 16; i++) {
                acc[i] = add2(acc[i], __shfl_xor_sync(0xffffffffu, acc[i], 4));
                acc[i] = add2(acc[i], __shfl_xor_sync(0xffffffffu, acc[i], 8));
                acc[i] = add2(acc[i], __shfl_xor_sync(0xffffffffu, acc[i], 16));
            }
            if (cks == 0) {
                ull* dst = &redk[(size_t)((ckb * 5 + cg) * 4 + cq) * 16];
#pragma unroll
                for (int i = 0; i < 16; i++) dst[i] = acc[i];
            }
        }
        __syncthreads();

        // ---- gates (tid<128) overlapped with shift-read (tid>=128) ----
        int spv0 = 0, swp0 = 0, swl0 = 0; float slv0 = 0.f; int sb0 = 0, sj0 = 0;
        int spv1 = 0, swp1 = 0, swl1 = 0; float slv1 = 0.f; int sb1 = 0, sj1 = 0;
        if (tid < 128) {
            int b = tid >> 4, u = tid & 15;
            int ucq = u >> 2, uc = u & 3, p = b >> 1, half = b & 1;
            float gate[5];
#pragma unroll
            for (int g = 0; g < 5; g++) {
                float s = 0.f;
#pragma unroll
                for (int kb = 0; kb < 4; kb++) {
                    ull v = redk[(size_t)((kb * 5 + g) * 4 + ucq) * 16 + uc * 4 + p];
                    s += half ? hi32(v) : lo32(v);
                }
                gate[g] = s + bcs[g * 16 + u];
            }
            int gb = gb0 + b, h = r * 16 + u;
            float cl = clcr[(b * 2 + 0) * 16 + u];
            float cr = clcr[(b * 2 + 1) * 16 + u];
            float cc = sigf(gate[1]) * cl + sigf(gate[2]) * cr + sigf(gate[0]) * tanhf(gate[4]);
            float hp = sigf(gate[3]) * tanhf(cc);
            g_states[gb][fsl[b]][h]     = cc;
            g_states[gb][fsl[b]][H + h] = hp;
            hloc[b * 16 + u] = hp;
        } else {
            int ii0 = tid - 128, ii1 = ii0 + 512;
            sb0 = ii0 / 96; sj0 = ii0 - sb0 * 96;
            {
                int idx = selidx[sb0];
                if (sj0 >= idx + 1 && sj0 <= n - 2) { spv0 = pmi[sb0 * 96 + sj0 + 1]; swp0 = 1; }
                if (sj0 >= idx + 1 && sj0 <= n - 3) { slv0 = lg[sb0 * 96 + sj0 + 1]; swl0 = 1; }
            }
            if (ii1 < NB * 96) {
                sb1 = ii1 / 96; sj1 = ii1 - sb1 * 96;
                int idx = selidx[sb1];
                if (sj1 >= idx + 1 && sj1 <= n - 2) { spv1 = pmi[sb1 * 96 + sj1 + 1]; swp1 = 1; }
                if (sj1 >= idx + 1 && sj1 <= n - 3) { slv1 = lg[sb1 * 96 + sj1 + 1]; swl1 = 1; }
            }
        }
        __syncthreads();

        // ---- shift-write + phase5 partials (local h' + neighbors) ----
        if (tid >= 128) {
            if (swp0) pmi[sb0 * 96 + sj0] = spv0;
            if (swl0) lg[sb0 * 96 + sj0] = slv0;
            if (swp1) pmi[sb1 * 96 + sj1] = spv1;
            if (swl1) lg[sb1 * 96 + sj1] = slv1;
        }
        if (tid < NB) pmi[tid * 96 + selidx[tid]] = fsl[tid];
        if (tid < 512) {
            int b = tid >> 6, j = (tid & 63) * 2;
            ull a0 = 0ull, a1 = 0ull;   // lo=pairA, hi=pairB for j and j+1
#pragma unroll 4
            for (int u = 0; u < 16; u++) {
                float ln = lnb[b * 16 + u];
                float hp = hloc[b * 16 + u];
                float rn = rnb[b * 16 + u];
                ull xa = pack2(ln, hp);     // weight row 16r+u: pairA uses lnb, pairB uses h'
                ull xb = pack2(hp, rn);     // weight row 256+16r+u: pairA uses h', pairB uses rnb
                float2 wa = *(const float2*)&ws1a[u * 128 + j];
                float2 wb = *(const float2*)&ws1b[u * 128 + j];
                a0 = fma2(pack2(wa.x, wa.x), xa, a0);
                a0 = fma2(pack2(wb.x, wb.x), xb, a0);
                a1 = fma2(pack2(wa.y, wa.y), xa, a1);
                a1 = fma2(pack2(wb.y, wb.y), xb, a1);
            }
            ulonglong2 st; st.x = a0; st.y = a1;
            *(ulonglong2*)&gp[(size_t)(b * CLG + r) * SEL + j] = st;
        }

        // ---- ONE group barrier: states + partials visible ----
        __syncthreads();
        tgt += CLG;
        if (tid == 0) {
            __threadfence();
            atomicAdd(&g_cnt[gq], 1u);
            while (atomicAdd(&g_cnt[gq], 0u) < tgt) {}
            __threadfence();
        }
        __syncthreads();

        // ---- replicated logit reconstruction ----
        if (tid < 512) {
            int b = tid >> 6, j0 = tid & 63;
            ull v0 = 0ull, v1 = 0ull;
#pragma unroll 4
            for (int rr = 0; rr < CLG; rr++) {
                const ull* src = &gp[(size_t)(b * CLG + rr) * SEL];
                v0 = add2(v0, __ldcg(&src[j0]));
                v1 = add2(v1, __ldcg(&src[j0 + 64]));
            }
            float yA = tanhf(lo32(v0) + bs1f[j0]) * ws2f[j0]
                     + tanhf(lo32(v1) + bs1f[j0 + 64]) * ws2f[j0 + 64];
            float yB = tanhf(hi32(v0) + bs1f[j0]) * ws2f[j0]
                     + tanhf(hi32(v1) + bs1f[j0 + 64]) * ws2f[j0 + 64];
#pragma unroll
            for (int o = 1; o < 32; o <<= 1) {
                yA += __shfl_xor_sync(0xffffffffu, yA, o);
                yB += __shfl_xor_sync(0xffffffffu, yB, o);
            }
            if ((tid & 31) == 0) {
                int w2 = (tid >> 5) & 1;
                red[(b * 2 + w2) * 2 + 0] = yA;
                red[(b * 2 + w2) * 2 + 1] = yB;
            }
        }
        __syncthreads();
        if (tid < 16) {
            int b = tid >> 1, s = tid & 1;
            int q = selidx[b] - 1 + s;
            if (q >= 0 && q <= n - 3)
                lg[b * 96 + q] = red[(b * 2 + 0) * 2 + s] + red[(b * 2 + 1) * 2 + s] + bs2v;
        }
        __syncthreads();
    }

    // ---- root hidden ----
    if (tid < 128) {
        int b = tid >> 4, u = tid & 15;
        g_hroot[gb0 + b][r * 16 + u] =
            __ldcg(&g_states[gb0 + b][pmi[b * 96]][H + r * 16 + u]);
    }

    // ---- reset barrier counters for next graph replay ----
    __syncthreads();
    if (tid == 0) {
        __threadfence();
        atomicAdd(&g_done[gq], 1u);
        if (r == 0) {
            while (atomicAdd(&g_done[gq], 0u) < CLG) {}
            g_cnt[gq] = 0u;
            g_done[gq] = 0u;
            __threadfence();
        }
    }
}

// ======================================================================
__global__ void mlp_l1(const float* __restrict__ Wm1, const float* __restrict__ bm1) {
    __shared__ float hsh[H];
    int b = blockIdx.y, c = blockIdx.x * 256 + threadIdx.x;
    if (threadIdx.x < H) hsh[threadIdx.x] = g_hroot[b][threadIdx.x];
    __syncthreads();
    float acc = bm1[c];
    const float* wp = Wm1 + c;
#pragma unroll 8
    for (int k = 0; k < H; k++) acc = __fmaf_rn(hsh[k], wp[k * MLPD], acc);
    g_x1[b][c] = fmaxf(acc, 0.0f);
}

__global__ void mlp_l2(const float* __restrict__ Wm2, const float* __restrict__ bm2) {
    __shared__ float x1s[MLPD];
    int b = blockIdx.y, c = blockIdx.x * 256 + threadIdx.x;
    for (int i = threadIdx.x; i < MLPD; i += 256) x1s[i] = g_x1[b][i];
    __syncthreads();
    float acc = bm2[c];
    const float* wp = Wm2 + c;
#pragma unroll 8
    for (int k = 0; k < MLPD; k++) acc = __fmaf_rn(x1s[k], wp[k * MLPD], acc);
    g_x2[b][c] = fmaxf(acc, 0.0f);
}

__global__ void mlp_l3(const float* __restrict__ Wout, const float* __restrict__ bout,
                       float* __restrict__ out) {
    __shared__ float red[4][NC];
    int b = blockIdx.x, tid = threadIdx.x;
    float p0 = 0.f, p1 = 0.f, p2 = 0.f;
    for (int k = tid; k < MLPD; k += 128) {
        float xv = g_x2[b][k];
        p0 = __fmaf_rn(xv, Wout[k * NC + 0], p0);
        p1 = __fmaf_rn(xv, Wout[k * NC + 1], p1);
        p2 = __fmaf_rn(xv, Wout[k * NC + 2], p2);
    }
    for (int o = 16; o; o >>= 1) {
        p0 += __shfl_xor_sync(0xffffffffu, p0, o);
        p1 += __shfl_xor_sync(0xffffffffu, p1, o);
        p2 += __shfl_xor_sync(0xffffffffu, p2, o);
    }
    int lane = tid & 31, wrp = tid >> 5;
    if (lane == 0) { red[wrp][0] = p0; red[wrp][1] = p1; red[wrp][2] = p2; }
    __syncthreads();
    if (tid < NC) {
        float s = bout[tid];
        for (int w = 0; w < 4; w++) s += red[w][tid];
        out[b * NC + tid] = s;
    }
}

// ======================================================================
extern "C" void kernel_launch(void* const* d_in, const int* in_sizes, int n_in,
                              void* d_out, int out_size) {
    const int*   sent = (const int*)d_in[0];
    const float* emb  = (const float*)d_in[2];
    const float* Wenc = (const float*)d_in[3];
    const float* benc = (const float*)d_in[4];
    const float* Wc   = (const float*)d_in[5];
    const float* bc   = (const float*)d_in[6];
    const float* Ws1  = (const float*)d_in[7];
    const float* bs1  = (const float*)d_in[8];
    const float* Ws2  = (const float*)d_in[9];
    const float* bs2  = (const float*)d_in[10];
    const float* Wm1  = (const float*)d_in[11];
    const float* bm1  = (const float*)d_in[12];
    const float* Wm2  = (const float*)d_in[13];
    const float* bm2  = (const float*)d_in[14];
    const float* Wout = (const float*)d_in[15];
    const float* bout = (const float*)d_in[16];

    static int smem_set = 0;
    if (!smem_set) {
        cudaFuncSetAttribute(scan_kernel, cudaFuncAttributeMaxDynamicSharedMemorySize, SMEM_SZ);
        smem_set = 1;
    }

    prof_pad_kernel<<<1, 32>>>();   // keeps ncu's profiled slot on scan_kernel
    encode_kernel<<<768, 128>>>(sent, emb, Wenc, benc);
    initsel_kernel<<<dim3(6, 64), 128>>>(Ws1, bs1, Ws2, bs2);
    scan_kernel<<<NGR * CLG, TPB, SMEM_SZ>>>(Wc, bc, Ws1, bs1, Ws2, bs2);
    mlp_l1<<<dim3(4, B), 256>>>(Wm1, bm1);
    mlp_l2<<<dim3(4, B), 256>>>(Wm2, bm2);
    mlp_l3<<<B, 128>>>(Wout, bout, (float*)d_out);
}

// round 14
// speedup vs baseline: 1.8606x; 1.1588x over previous
#include <cuda_runtime.h>
#include <math.h>

#define B   64
#define S   96
#define E   300
#define H   256
#define D   512
#define SEL 128
#define G5  1280
#define MLPD 1024
#define NC  3

#define CLG 16     // CTAs per group
#define NGR 8      // groups
#define NB  8      // batches per group
#define TPB 640
#define NS  97     // S + 1 spare slot

typedef unsigned long long ull;

__device__ __align__(16) float g_states[B][NS][D];
__device__ float g_logits0[B][S - 1];
__device__ float g_hroot[B][H];
__device__ float g_x1[B][MLPD];
__device__ float g_x2[B][MLPD];
__device__ __align__(16) ull g_part[2][NGR][NB][CLG][SEL];  // double-buffered partial logits
__device__ unsigned g_cnt[NGR];    // zero at load; reset by epilogue
__device__ unsigned g_done[NGR];

__device__ __forceinline__ float sigf(float x) { return 1.0f / (1.0f + expf(-x)); }
__device__ __forceinline__ ull fma2(ull a, ull b, ull c) {
    ull d; asm("fma.rn.f32x2 %0, %1, %2, %3;" : "=l"(d) : "l"(a), "l"(b), "l"(c)); return d;
}
__device__ __forceinline__ ull add2(ull a, ull b) {
    ull d; asm("add.rn.f32x2 %0, %1, %2;" : "=l"(d) : "l"(a), "l"(b)); return d;
}
__device__ __forceinline__ ull pack2(float x, float y) {
    ull d; asm("mov.b64 %0, {%1, %2};" : "=l"(d) : "f"(x), "f"(y)); return d;
}
__device__ __forceinline__ float lo32(ull v) { return __uint_as_float((unsigned)v); }
__device__ __forceinline__ float hi32(ull v) { return __uint_as_float((unsigned)(v >> 32)); }

// ---- scan dynamic smem layout (bytes) ----
#define O_W     0        // float Wsm[512][84]            172032
#define O_XS2   172032   // ull  xs2[4][512]              16384
#define O_WS1A  188416   // float ws1a[16][128]           8192
#define O_WS1B  196608   // float ws1b[16][128]           8192
#define O_REDK  204800   // ull  redk[80][16]             10240
#define O_LG    215040   // float lg[8][96]               3072
#define O_PM    218112   // int  pm[8][96]                3072
#define O_CLCR  221184   // float clcr[8][2][16]          1024
#define O_BCS   222208   // float bcs[80]                 384
#define O_HLOC  222592   // float hloc[8][16]             512
#define O_LNB   223104   // float lnb[8][16]              512
#define O_RNB   223616   // float rnb[8][16]              512
#define O_BS1F  224128   // float bs1f[128]               512
#define O_WS2F  224640   // float ws2f[128]               512
#define O_RED   225152   // float red[8][2][2]            128
#define O_MISC  225280   // ints/floats                   512
#define SMEM_SZ 225792

// initsel dynamic smem: hs[17][256] floats + pht[512][8] ulls
#define ISEL_HS   0
#define ISEL_PHT  17408
#define ISEL_SMEM (17408 + 32768)

__global__ void prof_pad_kernel() {}

// ======================================================================
// encode: f32x2 packed (2 cols per ull), pre-splatted x in smem.
// Per-column accumulation order identical to prior rounds (bit-exact).
// ======================================================================
__global__ void encode_kernel(const int* __restrict__ sent, const float* __restrict__ emb,
                              const float* __restrict__ Wenc, const float* __restrict__ benc) {
    __shared__ __align__(16) ull xsh2[8 * E];   // pre-splatted (x,x), 19.2KB
    __shared__ int tok[8];
    int row0 = blockIdx.x * 8, tid = threadIdx.x;
    if (tid < 8) tok[tid] = sent[row0 + tid];
    __syncthreads();
    for (int i = tid; i < 8 * E; i += 128) {
        int r = i / E, k = i - r * E;
        float v = emb[(long)tok[r] * E + k];
        xsh2[i] = pack2(v, v);
    }
    __syncthreads();
    int c = tid * 4;
    ull acc0[8], acc1[8];
#pragma unroll
    for (int r = 0; r < 8; r++) { acc0[r] = 0ull; acc1[r] = 0ull; }
    for (int k = 0; k < E; k += 2) {
        float4 wa = *(const float4*)&Wenc[k * D + c];
        float4 wb = *(const float4*)&Wenc[(k + 1) * D + c];
        ull wa0 = pack2(wa.x, wa.y), wa1 = pack2(wa.z, wa.w);
        ull wb0 = pack2(wb.x, wb.y), wb1 = pack2(wb.z, wb.w);
#pragma unroll
        for (int r = 0; r < 8; r++) {
            ulonglong2 xq = *(const ulonglong2*)&xsh2[r * E + k];
            acc0[r] = fma2(wa0, xq.x, acc0[r]);
            acc1[r] = fma2(wa1, xq.x, acc1[r]);
            acc0[r] = fma2(wb0, xq.y, acc0[r]);
            acc1[r] = fma2(wb1, xq.y, acc1[r]);
        }
    }
    float4 bv = *(const float4*)&benc[c];
#pragma unroll
    for (int r = 0; r < 8; r++) {
        float4 o;
        o.x = __fadd_rn(lo32(acc0[r]), bv.x);
        o.y = __fadd_rn(hi32(acc0[r]), bv.y);
        o.z = __fadd_rn(lo32(acc1[r]), bv.z);
        o.w = __fadd_rn(hi32(acc1[r]), bv.w);
        int gr = row0 + r, b = gr / S, s = gr - b * S;
        *(float4*)&g_states[b][s][c] = o;
    }
}

// ======================================================================
// initsel: k-outer, weights read ONCE; pairs (p, p+8) packed in f32x2.
// ======================================================================
__global__ void initsel_kernel(const float* __restrict__ Ws1, const float* __restrict__ bs1,
                               const float* __restrict__ Ws2, const float* __restrict__ bs2) {
    extern __shared__ char ism[];
    float* hs  = (float*)(ism + ISEL_HS);    // [17][256]
    ull*   pht = (ull*)(ism + ISEL_PHT);     // [512][8]
    __shared__ float red[16][4];
    int b = blockIdx.y, p0 = blockIdx.x * 16, tid = threadIdx.x;
    int nrows = min(17, S - p0);
    for (int i = tid; i < 17 * 256; i += 128) {
        int r = i >> 8, k = i & 255;
        hs[i] = (r < nrows) ? g_states[b][p0 + r][H + k] : 0.0f;
    }
    __syncthreads();
    for (int i = tid; i < 4096; i += 128) {
        int k = i >> 3, p = i & 7;
        int rr = (k >= 256) ? 1 : 0, kk = k & 255;
        pht[i] = pack2(hs[(p + rr) * 256 + kk], hs[(p + 8 + rr) * 256 + kk]);
    }
    __syncthreads();
    ull acc[8];
#pragma unroll
    for (int p = 0; p < 8; p++) acc[p] = 0ull;
    const float* wp = Ws1 + tid;
    for (int k = 0; k < 512; k++) {
        float w = wp[(size_t)k * SEL];
        ull ws = pack2(w, w);
        const ull* px = &pht[k * 8];
        ulonglong2 q0 = *(const ulonglong2*)&px[0];
        ulonglong2 q1 = *(const ulonglong2*)&px[2];
        ulonglong2 q2 = *(const ulonglong2*)&px[4];
        ulonglong2 q3 = *(const ulonglong2*)&px[6];
        acc[0] = fma2(ws, q0.x, acc[0]); acc[1] = fma2(ws, q0.y, acc[1]);
        acc[2] = fma2(ws, q1.x, acc[2]); acc[3] = fma2(ws, q1.y, acc[3]);
        acc[4] = fma2(ws, q2.x, acc[4]); acc[5] = fma2(ws, q2.y, acc[5]);
        acc[6] = fma2(ws, q3.x, acc[6]); acc[7] = fma2(ws, q3.y, acc[7]);
    }
    float b1 = bs1[tid], w2 = Ws2[tid];
    int lane = tid & 31, wrp = tid >> 5;
    int npairs = min(16, (S - 1) - p0);
#pragma unroll
    for (int p = 0; p < 16; p++) {
        float s = (p < 8) ? lo32(acc[p]) : hi32(acc[p - 8]);
        float y = tanhf(s + b1) * w2;
        for (int o = 16; o; o >>= 1) y += __shfl_xor_sync(0xffffffffu, y, o);
        if (lane == 0) red[p][wrp] = y;
    }
    __syncthreads();
    if (tid < npairs)
        g_logits0[b][p0 + tid] = red[tid][0] + red[tid][1] + red[tid][2] + red[tid][3] + bs2[0];
}

// ======================================================================
// Persistent scan: identical to R13 except the post-barrier logit
// reconstruction (ulonglong2 gathers + fixed-order tree rank-sum).
// ======================================================================
__global__ void __launch_bounds__(TPB, 1)
scan_kernel(const float* __restrict__ Wc,  const float* __restrict__ bc,
            const float* __restrict__ Ws1, const float* __restrict__ bs1,
            const float* __restrict__ Ws2, const float* __restrict__ bs2) {
    extern __shared__ char dsm[];
    float* Wsm  = (float*)(dsm + O_W);
    ull*   xs2  = (ull*)(dsm + O_XS2);
    float* ws1a = (float*)(dsm + O_WS1A);
    float* ws1b = (float*)(dsm + O_WS1B);
    ull*   redk = (ull*)(dsm + O_REDK);
    float* lg   = (float*)(dsm + O_LG);
    int*   pmi  = (int*)(dsm + O_PM);
    float* clcr = (float*)(dsm + O_CLCR);
    float* bcs  = (float*)(dsm + O_BCS);
    float* hloc = (float*)(dsm + O_HLOC);
    float* lnb  = (float*)(dsm + O_LNB);
    float* rnb  = (float*)(dsm + O_RNB);
    float* bs1f = (float*)(dsm + O_BS1F);
    float* ws2f = (float*)(dsm + O_WS2F);
    float* red  = (float*)(dsm + O_RED);
    int*   misc = (int*)(dsm + O_MISC);
    int* selidx = misc;       int* sLa = misc + 8;  int* sRa = misc + 16;
    int* frs    = misc + 24;  int* fsl = misc + 32;

    int tid = threadIdx.x;
    int r   = blockIdx.x & (CLG - 1);
    int gq  = blockIdx.x >> 4;
    int gb0 = gq * NB;

    for (int i = tid; i < 512 * 20; i += TPB) {
        int k = i / 20, q = i - k * 20;
        int g = q >> 2, u4 = (q & 3) * 4;
        float4 w = *(const float4*)&Wc[(size_t)k * G5 + g * 256 + r * 16 + u4];
        *(float4*)&Wsm[k * 84 + q * 4] = w;
    }
    for (int i = tid; i < 2048; i += TPB) {
        int u = i >> 7, j = i & 127;
        ws1a[i] = Ws1[(size_t)(r * 16 + u) * SEL + j];
        ws1b[i] = Ws1[(size_t)(256 + r * 16 + u) * SEL + j];
    }
    if (tid < 128) { bs1f[tid] = bs1[tid]; ws2f[tid] = Ws2[tid]; }
    if (tid < 80) {
        int g = tid >> 4, u = tid & 15;
        bcs[tid] = bc[g * 256 + r * 16 + u];
    }
    if (tid < 8) frs[tid] = 96;
    for (int i = tid; i < NB * (S - 1); i += TPB) {
        int b = i / (S - 1), j = i - b * (S - 1);
        lg[b * 96 + j] = g_logits0[gb0 + b][j];
    }
    for (int i = tid; i < NB * S; i += TPB) {
        int b = i / S, j = i - b * S;
        pmi[b * 96 + j] = j;
    }
    float bs2v = bs2[0];
    __syncthreads();

    int wid = tid >> 5, lane = tid & 31;
    int cg  = wid % 5, ckb = wid / 5;
    int cks = lane >> 2, cq = lane & 3;
    int wbase = cg * 16 + cq * 4;

    unsigned tgt = 0;

    for (int t = 0; t < S - 1; t++) {
        int n = S - t, np = n - 1;
        int par = t & 1;
        ull* gp = &g_part[par][gq][0][0][0];

        // ---- argmax (replicated) ----
        if (tid < 256) {
            int b = tid >> 5, ln = tid & 31;
            float best = -1e30f; int bi = 0;
            for (int j = ln; j < np; j += 32) {
                float v = lg[b * 96 + j];
                if (v > best) { best = v; bi = j; }
            }
            for (int o = 16; o; o >>= 1) {
                float ov = __shfl_xor_sync(0xffffffffu, best, o);
                int   oi = __shfl_xor_sync(0xffffffffu, bi, o);
                if (ov > best || (ov == best && oi < bi)) { best = ov; bi = oi; }
            }
            if (ln == 0) {
                int sl = pmi[b * 96 + bi], sr = pmi[b * 96 + bi + 1];
                selidx[b] = bi; sLa[b] = sl; sRa[b] = sr;
                fsl[b] = frs[b];
                frs[b] = sr;
            }
        }
        __syncthreads();

        // ---- staging ----
        if (tid < 512) {
            int p = tid >> 7, kq = (tid & 127) << 2;
            int b0 = 2 * p, b1 = 2 * p + 1;
            int slot0 = (kq < H) ? sLa[b0] : sRa[b0];
            int slot1 = (kq < H) ? sLa[b1] : sRa[b1];
            int col = (kq < H) ? (H + kq) : kq;
            float4 a = __ldcg((const float4*)&g_states[gb0 + b0][slot0][col]);
            float4 c = __ldcg((const float4*)&g_states[gb0 + b1][slot1][col]);
            xs2[p * 512 + kq]     = pack2(a.x, c.x);
            xs2[p * 512 + kq + 1] = pack2(a.y, c.y);
            xs2[p * 512 + kq + 2] = pack2(a.z, c.z);
            xs2[p * 512 + kq + 3] = pack2(a.w, c.w);
        } else {
            int i0 = (tid - 512) * 2;
#pragma unroll
            for (int s = 0; s < 2; s++) {
                int i = i0 + s;
                int b = i >> 5, half = (i >> 4) & 1, u = i & 15;
                clcr[(b * 2 + half) * 16 + u] =
                    __ldcg(&g_states[gb0 + b][half ? sRa[b] : sLa[b]][r * 16 + u]);
            }
        }
        if (tid < 256) {
            int b = tid >> 5, rest = tid & 31;
            int half = rest >> 4, u = rest & 15;
            int idx = selidx[b];
            float v = 0.f;
            if (half == 0) {
                if (idx >= 1)
                    v = __ldcg(&g_states[gb0 + b][pmi[b * 96 + idx - 1]][H + r * 16 + u]);
                lnb[b * 16 + u] = v;
            } else {
                if (idx <= n - 3)
                    v = __ldcg(&g_states[gb0 + b][pmi[b * 96 + idx + 2]][H + r * 16 + u]);
                rnb[b * 16 + u] = v;
            }
        }
        __syncthreads();

        // ---- compose ----
        {
            ull acc[16];
#pragma unroll
            for (int i = 0; i < 16; i++) acc[i] = 0ull;
#pragma unroll 4
            for (int m = 0; m < 16; m++) {
                int k = ckb * 128 + m * 8 + cks;
                float4 w4 = *(const float4*)&Wsm[k * 84 + wbase];
                ull x0 = xs2[k], x1 = xs2[512 + k], x2 = xs2[1024 + k], x3 = xs2[1536 + k];
                ull w;
                w = pack2(w4.x, w4.x);
                acc[0] = fma2(w, x0, acc[0]); acc[1] = fma2(w, x1, acc[1]);
                acc[2] = fma2(w, x2, acc[2]); acc[3] = fma2(w, x3, acc[3]);
                w = pack2(w4.y, w4.y);
                acc[4] = fma2(w, x0, acc[4]); acc[5] = fma2(w, x1, acc[5]);
                acc[6] = fma2(w, x2, acc[6]); acc[7] = fma2(w, x3, acc[7]);
                w = pack2(w4.z, w4.z);
                acc[8] = fma2(w, x0, acc[8]); acc[9] = fma2(w, x1, acc[9]);
                acc[10] = fma2(w, x2, acc[10]); acc[11] = fma2(w, x3, acc[11]);
                w = pack2(w4.w, w4.w);
                acc[12] = fma2(w, x0, acc[12]); acc[13] = fma2(w, x1, acc[13]);
                acc[14] = fma2(w, x2, acc[14]); acc[15] = fma2(w, x3, acc[15]);
            }
#pragma unroll
            for (int i = 0; i < 16; i++) {
                acc[i] = add2(acc[i], __shfl_xor_sync(0xffffffffu, acc[i], 4));
                acc[i] = add2(acc[i], __shfl_xor_sync(0xffffffffu, acc[i], 8));
                acc[i] = add2(acc[i], __shfl_xor_sync(0xffffffffu, acc[i], 16));
            }
            if (cks == 0) {
                ull* dst = &redk[(size_t)((ckb * 5 + cg) * 4 + cq) * 16];
#pragma unroll
                for (int i = 0; i < 16; i++) dst[i] = acc[i];
            }
        }
        __syncthreads();

        // ---- gates overlapped with shift-read ----
        int spv0 = 0, swp0 = 0, swl0 = 0; float slv0 = 0.f; int sb0 = 0, sj0 = 0;
        int spv1 = 0, swp1 = 0, swl1 = 0; float slv1 = 0.f; int sb1 = 0, sj1 = 0;
        if (tid < 128) {
            int b = tid >> 4, u = tid & 15;
            int ucq = u >> 2, uc = u & 3, p = b >> 1, half = b & 1;
            float gate[5];
#pragma unroll
            for (int g = 0; g < 5; g++) {
                float s = 0.f;
#pragma unroll
                for (int kb = 0; kb < 4; kb++) {
                    ull v = redk[(size_t)((kb * 5 + g) * 4 + ucq) * 16 + uc * 4 + p];
                    s += half ? hi32(v) : lo32(v);
                }
                gate[g] = s + bcs[g * 16 + u];
            }
            int gb = gb0 + b, h = r * 16 + u;
            float cl = clcr[(b * 2 + 0) * 16 + u];
            float cr = clcr[(b * 2 + 1) * 16 + u];
            float cc = sigf(gate[1]) * cl + sigf(gate[2]) * cr + sigf(gate[0]) * tanhf(gate[4]);
            float hp = sigf(gate[3]) * tanhf(cc);
            g_states[gb][fsl[b]][h]     = cc;
            g_states[gb][fsl[b]][H + h] = hp;
            hloc[b * 16 + u] = hp;
        } else {
            int ii0 = tid - 128, ii1 = ii0 + 512;
            sb0 = ii0 / 96; sj0 = ii0 - sb0 * 96;
            {
                int idx = selidx[sb0];
                if (sj0 >= idx + 1 && sj0 <= n - 2) { spv0 = pmi[sb0 * 96 + sj0 + 1]; swp0 = 1; }
                if (sj0 >= idx + 1 && sj0 <= n - 3) { slv0 = lg[sb0 * 96 + sj0 + 1]; swl0 = 1; }
            }
            if (ii1 < NB * 96) {
                sb1 = ii1 / 96; sj1 = ii1 - sb1 * 96;
                int idx = selidx[sb1];
                if (sj1 >= idx + 1 && sj1 <= n - 2) { spv1 = pmi[sb1 * 96 + sj1 + 1]; swp1 = 1; }
                if (sj1 >= idx + 1 && sj1 <= n - 3) { slv1 = lg[sb1 * 96 + sj1 + 1]; swl1 = 1; }
            }
        }
        __syncthreads();

        // ---- shift-write + phase5 partials ----
        if (tid >= 128) {
            if (swp0) pmi[sb0 * 96 + sj0] = spv0;
            if (swl0) lg[sb0 * 96 + sj0] = slv0;
            if (swp1) pmi[sb1 * 96 + sj1] = spv1;
            if (swl1) lg[sb1 * 96 + sj1] = slv1;
        }
        if (tid < NB) pmi[tid * 96 + selidx[tid]] = fsl[tid];
        if (tid < 512) {
            int b = tid >> 6, j = (tid & 63) * 2;
            ull a0 = 0ull, a1 = 0ull;
#pragma unroll 4
            for (int u = 0; u < 16; u++) {
                float ln = lnb[b * 16 + u];
                float hp = hloc[b * 16 + u];
                float rn = rnb[b * 16 + u];
                ull xa = pack2(ln, hp);
                ull xb = pack2(hp, rn);
                float2 wa = *(const float2*)&ws1a[u * 128 + j];
                float2 wb = *(const float2*)&ws1b[u * 128 + j];
                a0 = fma2(pack2(wa.x, wa.x), xa, a0);
                a0 = fma2(pack2(wb.x, wb.x), xb, a0);
                a1 = fma2(pack2(wa.y, wa.y), xa, a1);
                a1 = fma2(pack2(wb.y, wb.y), xb, a1);
            }
            ulonglong2 st; st.x = a0; st.y = a1;
            *(ulonglong2*)&gp[(size_t)(b * CLG + r) * SEL + j] = st;
        }

        // ---- ONE group barrier ----
        __syncthreads();
        tgt += CLG;
        if (tid == 0) {
            __threadfence();
            atomicAdd(&g_cnt[gq], 1u);
            while (atomicAdd(&g_cnt[gq], 0u) < tgt) {}
            __threadfence();
        }
        __syncthreads();

        // ---- replicated logit reconstruction (vectorized, tree order) ----
        if (tid < 512) {
            int b = tid >> 6, j0 = tid & 63;
            const ull* src = &gp[(size_t)(b * CLG) * SEL + j0 * 2];
            ull ax0 = 0ull, ax1 = 0ull, ax2 = 0ull, ax3 = 0ull;
            ull ay0 = 0ull, ay1 = 0ull, ay2 = 0ull, ay3 = 0ull;
#pragma unroll
            for (int rr = 0; rr < CLG; rr += 4) {
                ulonglong2 q0 = __ldcg((const ulonglong2*)(src + (size_t)(rr + 0) * SEL));
                ulonglong2 q1 = __ldcg((const ulonglong2*)(src + (size_t)(rr + 1) * SEL));
                ulonglong2 q2 = __ldcg((const ulonglong2*)(src + (size_t)(rr + 2) * SEL));
                ulonglong2 q3 = __ldcg((const ulonglong2*)(src + (size_t)(rr + 3) * SEL));
                ax0 = add2(ax0, q0.x); ay0 = add2(ay0, q0.y);
                ax1 = add2(ax1, q1.x); ay1 = add2(ay1, q1.y);
                ax2 = add2(ax2, q2.x); ay2 = add2(ay2, q2.y);
                ax3 = add2(ax3, q3.x); ay3 = add2(ay3, q3.y);
            }
            ull vx = add2(add2(ax0, ax1), add2(ax2, ax3));
            ull vy = add2(add2(ay0, ay1), add2(ay2, ay3));
            float2 b2 = *(const float2*)&bs1f[j0 * 2];
            float2 w2 = *(const float2*)&ws2f[j0 * 2];
            float yA = tanhf(lo32(vx) + b2.x) * w2.x + tanhf(lo32(vy) + b2.y) * w2.y;
            float yB = tanhf(hi32(vx) + b2.x) * w2.x + tanhf(hi32(vy) + b2.y) * w2.y;
#pragma unroll
            for (int o = 1; o < 32; o <<= 1) {
                yA += __shfl_xor_sync(0xffffffffu, yA, o);
                yB += __shfl_xor_sync(0xffffffffu, yB, o);
            }
            if ((tid & 31) == 0) {
                int w = (tid >> 5) & 1;
                red[(b * 2 + w) * 2 + 0] = yA;
                red[(b * 2 + w) * 2 + 1] = yB;
            }
        }
        __syncthreads();
        if (tid < 16) {
            int b = tid >> 1, s = tid & 1;
            int q = selidx[b] - 1 + s;
            if (q >= 0 && q <= n - 3)
                lg[b * 96 + q] = red[(b * 2 + 0) * 2 + s] + red[(b * 2 + 1) * 2 + s] + bs2v;
        }
        __syncthreads();
    }

    if (tid < 128) {
        int b = tid >> 4, u = tid & 15;
        g_hroot[gb0 + b][r * 16 + u] =
            __ldcg(&g_states[gb0 + b][pmi[b * 96]][H + r * 16 + u]);
    }

    __syncthreads();
    if (tid == 0) {
        __threadfence();
        atomicAdd(&g_done[gq], 1u);
        if (r == 0) {
            while (atomicAdd(&g_done[gq], 0u) < CLG) {}
            g_cnt[gq] = 0u;
            g_done[gq] = 0u;
            __threadfence();
        }
    }
}

// ======================================================================
// MLP: batch-tiled, k-split, batch-pair f32x2
// ======================================================================
__global__ void mlp_l1(const float* __restrict__ Wm1, const float* __restrict__ bm1) {
    __shared__ __align__(16) float xt[H * 8];       // xt[k*8+b], 8KB
    __shared__ ull part2[4 * 64 * 4];               // [ks][col][bp], 8KB
    int bx = blockIdx.x, by = blockIdx.y, tid = threadIdx.x;
    for (int i = tid; i < H * 8; i += 256) {
        int k = i >> 3, b = i & 7;
        xt[i] = g_hroot[by * 8 + b][k];
    }
    __syncthreads();
    int col = tid & 63, ks = tid >> 6;
    int c = bx * 64 + col;
    ull acc[4];
#pragma unroll
    for (int q = 0; q < 4; q++) acc[q] = 0ull;
    for (int k = ks * 64; k < ks * 64 + 64; k++) {
        float w = Wm1[(size_t)k * MLPD + c];
        ull ws = pack2(w, w);
        const ull* xp = (const ull*)&xt[k * 8];
        acc[0] = fma2(ws, xp[0], acc[0]);
        acc[1] = fma2(ws, xp[1], acc[1]);
        acc[2] = fma2(ws, xp[2], acc[2]);
        acc[3] = fma2(ws, xp[3], acc[3]);
    }
#pragma unroll
    for (int q = 0; q < 4; q++) part2[(ks * 64 + col) * 4 + q] = acc[q];
    __syncthreads();
    for (int i = tid; i < 512; i += 256) {
        int cc = i >> 3, b = i & 7;
        int q = b >> 1, half = b & 1;
        float s = 0.f;
#pragma unroll
        for (int kk = 0; kk < 4; kk++) {
            ull v = part2[(kk * 64 + cc) * 4 + q];
            s += half ? hi32(v) : lo32(v);
        }
        g_x1[by * 8 + b][bx * 64 + cc] = fmaxf(s + bm1[bx * 64 + cc], 0.0f);
    }
}

__global__ void mlp_l2(const float* __restrict__ Wm2, const float* __restrict__ bm2) {
    __shared__ __align__(16) float xt[MLPD * 8];    // 32KB
    __shared__ ull part2[4 * 64 * 4];               // 8KB
    int bx = blockIdx.x, by = blockIdx.y, tid = threadIdx.x;
    for (int i = tid; i < MLPD * 8; i += 256) {
        int b = i >> 10, k = i & 1023;
        xt[k * 8 + b] = g_x1[by * 8 + b][k];
    }
    __syncthreads();
    int col = tid & 63, ks = tid >> 6;
    int c = bx * 64 + col;
    ull acc[4];
#pragma unroll
    for (int q = 0; q < 4; q++) acc[q] = 0ull;
    for (int k = ks * 256; k < ks * 256 + 256; k++) {
        float w = Wm2[(size_t)k * MLPD + c];
        ull ws = pack2(w, w);
        const ull* xp = (const ull*)&xt[k * 8];
        acc[0] = fma2(ws, xp[0], acc[0]);
        acc[1] = fma2(ws, xp[1], acc[1]);
        acc[2] = fma2(ws, xp[2], acc[2]);
        acc[3] = fma2(ws, xp[3], acc[3]);
    }
#pragma unroll
    for (int q = 0; q < 4; q++) part2[(ks * 64 + col) * 4 + q] = acc[q];
    __syncthreads();
    for (int i = tid; i < 512; i += 256) {
        int cc = i >> 3, b = i & 7;
        int q = b >> 1, half = b & 1;
        float s = 0.f;
#pragma unroll
        for (int kk = 0; kk < 4; kk++) {
            ull v = part2[(kk * 64 + cc) * 4 + q];
            s += half ? hi32(v) : lo32(v);
        }
        g_x2[by * 8 + b][bx * 64 + cc] = fmaxf(s + bm2[bx * 64 + cc], 0.0f);
    }
}

__global__ void mlp_l3(const float* __restrict__ Wout, const float* __restrict__ bout,
                       float* __restrict__ out) {
    __shared__ float red[4][NC];
    int b = blockIdx.x, tid = threadIdx.x;
    float p0 = 0.f, p1 = 0.f, p2 = 0.f;
    for (int k = tid; k < MLPD; k += 128) {
        float xv = g_x2[b][k];
        p0 = __fmaf_rn(xv, Wout[k * NC + 0], p0);
        p1 = __fmaf_rn(xv, Wout[k * NC + 1], p1);
        p2 = __fmaf_rn(xv, Wout[k * NC + 2], p2);
    }
    for (int o = 16; o; o >>= 1) {
        p0 += __shfl_xor_sync(0xffffffffu, p0, o);
        p1 += __shfl_xor_sync(0xffffffffu, p1, o);
        p2 += __shfl_xor_sync(0xffffffffu, p2, o);
    }
    int lane = tid & 31, wrp = tid >> 5;
    if (lane == 0) { red[wrp][0] = p0; red[wrp][1] = p1; red[wrp][2] = p2; }
    __syncthreads();
    if (tid < NC) {
        float s = bout[tid];
        for (int w = 0; w < 4; w++) s += red[w][tid];
        out[b * NC + tid] = s;
    }
}

// ======================================================================
extern "C" void kernel_launch(void* const* d_in, const int* in_sizes, int n_in,
                              void* d_out, int out_size) {
    const int*   sent = (const int*)d_in[0];
    const float* emb  = (const float*)d_in[2];
    const float* Wenc = (const float*)d_in[3];
    const float* benc = (const float*)d_in[4];
    const float* Wc   = (const float*)d_in[5];
    const float* bc   = (const float*)d_in[6];
    const float* Ws1  = (const float*)d_in[7];
    const float* bs1  = (const float*)d_in[8];
    const float* Ws2  = (const float*)d_in[9];
    const float* bs2  = (const float*)d_in[10];
    const float* Wm1  = (const float*)d_in[11];
    const float* bm1  = (const float*)d_in[12];
    const float* Wm2  = (const float*)d_in[13];
    const float* bm2  = (const float*)d_in[14];
    const float* Wout = (const float*)d_in[15];
    const float* bout = (const float*)d_in[16];

    static int smem_set = 0;
    if (!smem_set) {
        cudaFuncSetAttribute(scan_kernel, cudaFuncAttributeMaxDynamicSharedMemorySize, SMEM_SZ);
        cudaFuncSetAttribute(initsel_kernel, cudaFuncAttributeMaxDynamicSharedMemorySize, ISEL_SMEM);
        smem_set = 1;
    }

    prof_pad_kernel<<<1, 32>>>();   // keeps ncu's profiled slot on scan_kernel
    encode_kernel<<<768, 128>>>(sent, emb, Wenc, benc);
    initsel_kernel<<<dim3(6, 64), 128, ISEL_SMEM>>>(Ws1, bs1, Ws2, bs2);
    scan_kernel<<<NGR * CLG, TPB, SMEM_SZ>>>(Wc, bc, Ws1, bs1, Ws2, bs2);
    mlp_l1<<<dim3(16, 8), 256>>>(Wm1, bm1);
    mlp_l2<<<dim3(16, 8), 256>>>(Wm2, bm2);
    mlp_l3<<<B, 128>>>(Wout, bout, (float*)d_out);
}